// round 11
// baseline (speedup 1.0000x reference)
#include <cuda_runtime.h>
#include <cuda_fp16.h>
#include <cstdint>
#include <math.h>

#define BATCH 2
#define SEQ 2048
#define DM 1024
#define NH 16
#define HD 64
#define EPSV 1e-6f

// ---------------------------------------------------------------------------
// Scratch (__device__ globals: allocation-free rule)
// ---------------------------------------------------------------------------
__device__ __half g_xh[BATCH * SEQ * DM];
__device__ __half g_xl[BATCH * SEQ * DM];
__device__ __half g_wqh[DM * DM], g_wkh[DM * DM], g_wvh[DM * DM], g_woh[DM * DM];
__device__ __half g_qbh[BATCH * NH * SEQ * HD], g_qbl[BATCH * NH * SEQ * HD];
__device__ __half g_kbh[BATCH * NH * SEQ * HD];
__device__ __half g_vth[BATCH * NH * HD * SEQ];      // [b,h,d,s] fp16
__device__ __half g_ath[BATCH * SEQ * DM], g_atl[BATCH * SEQ * DM];

// ---------------------------------------------------------------------------
// Helpers (non-'a' instructions only: legal under compute_103)
// ---------------------------------------------------------------------------
__device__ __forceinline__ uint32_t smem_to_u32(const void* p) {
    uint32_t a;
    asm("{ .reg .u64 t; cvta.to.shared.u64 t, %1; cvt.u32.u64 %0, t; }" : "=r"(a) : "l"(p));
    return a;
}
#define SMEM_SWIZZLE_128B(o) ((o) ^ (((o) >> 3) & 0x70))

#define CP_ASYNC16(dst, src) \
    asm volatile("cp.async.cg.shared.global [%0], [%1], 16;" :: "r"(dst), "l"(src))
#define CP_COMMIT() asm volatile("cp.async.commit_group;" ::: "memory")
#define CP_WAIT0()  asm volatile("cp.async.wait_group 0;" ::: "memory")
#define CP_WAIT1()  asm volatile("cp.async.wait_group 1;" ::: "memory")

__device__ __forceinline__ void ldm_x4(uint32_t* r, uint32_t addr) {
    asm volatile("ldmatrix.sync.aligned.m8n8.x4.shared.b16 {%0,%1,%2,%3}, [%4];"
                 : "=r"(r[0]), "=r"(r[1]), "=r"(r[2]), "=r"(r[3]) : "r"(addr));
}
__device__ __forceinline__ void mma_f16(float* d, const uint32_t* a, const uint32_t* b) {
    asm volatile("mma.sync.aligned.m16n8k16.row.col.f32.f16.f16.f32 "
        "{%0,%1,%2,%3}, {%4,%5,%6,%7}, {%8,%9}, {%0,%1,%2,%3};"
        : "+f"(d[0]), "+f"(d[1]), "+f"(d[2]), "+f"(d[3])
        : "r"(a[0]), "r"(a[1]), "r"(a[2]), "r"(a[3]), "r"(b[0]), "r"(b[1]));
}
__device__ __forceinline__ uint32_t h2u(__half2 h) { return *reinterpret_cast<uint32_t*>(&h); }

// ---------------------------------------------------------------------------
__global__ void split_f32h(const float* __restrict__ in, __half* __restrict__ h,
                           __half* __restrict__ l, int n)
{
    int i = blockIdx.x * blockDim.x + threadIdx.x;
    if (i < n) {
        float x = in[i];
        __half hi = __float2half_rn(x);
        h[i] = hi;
        l[i] = __float2half_rn(x - __half2float(hi));
    }
}

__global__ void conv_weights(const float* __restrict__ wq, const float* __restrict__ wk,
                             const float* __restrict__ wv, const float* __restrict__ wo,
                             __half* __restrict__ oq, __half* __restrict__ ok,
                             __half* __restrict__ ov, __half* __restrict__ oo)
{
    int i = blockIdx.x * blockDim.x + threadIdx.x;
    int sel = i >> 20, li = i & ((1 << 20) - 1);
    const float* src = sel == 0 ? wq : sel == 1 ? wk : sel == 2 ? wv : wo;
    __half* dst = sel == 0 ? oq : sel == 1 ? ok : sel == 2 ? ov : oo;
    dst[li] = __float2half_rn(src[li]);
}

// ---------------------------------------------------------------------------
// Shared GEMM mainloop: 128x128 tile, BK=64, 2-pass split A(hi+lo) x B(hi).
// ---------------------------------------------------------------------------
#define GEMM_MAINLOOP(Ahp, Alp, Bhp)                                                   \
    auto AH_OFF = [&](int buf) { return base + (uint32_t)buf * 49152u; };              \
    auto AL_OFF = [&](int buf) { return AH_OFF(buf) + 16384u; };                       \
    auto BH_OFF = [&](int buf) { return AH_OFF(buf) + 32768u; };                       \
    float acc[2][8][4];                                                                \
    _Pragma("unroll") for (int i = 0; i < 2; i++)                                      \
        _Pragma("unroll") for (int j = 0; j < 8; j++)                                  \
            _Pragma("unroll") for (int q = 0; q < 4; q++) acc[i][j][q] = 0.f;          \
    auto load_chunk = [&](int c) {                                                     \
        int k0 = c << 6;                                                               \
        int buf = c & 1;                                                               \
        for (int idx = tid; idx < 3072; idx += 256) {                                  \
            int sel = idx >> 10;                                                       \
            int li = idx & 1023;                                                       \
            int row = li >> 3, seg = li & 7;                                           \
            const __half* src;                                                         \
            uint32_t dstb;                                                             \
            if (sel == 0)      { src = Ahp + (size_t)(bm + row) * DM + k0; dstb = AH_OFF(buf); } \
            else if (sel == 1) { src = Alp + (size_t)(bm + row) * DM + k0; dstb = AL_OFF(buf); } \
            else               { src = Bhp + (size_t)(bn + row) * DM + k0; dstb = BH_OFF(buf); } \
            CP_ASYNC16(dstb + SMEM_SWIZZLE_128B((uint32_t)(row * 128 + seg * 16)), src + seg * 8); \
        }                                                                              \
        CP_COMMIT();                                                                   \
    };                                                                                 \
    load_chunk(0);                                                                     \
    const int lr = lane & 15, kh = lane >> 4;                                          \
    const int kc = DM >> 6;                                                            \
    for (int c = 0; c < kc; c++) {                                                     \
        if (c + 1 < kc) { load_chunk(c + 1); CP_WAIT1(); }                             \
        else            { CP_WAIT0(); }                                                \
        __syncthreads();                                                               \
        int buf = c & 1;                                                               \
        _Pragma("unroll") for (int kk = 0; kk < 4; kk++) {                             \
            uint32_t aH[2][4], aL[2][4];                                               \
            _Pragma("unroll") for (int i = 0; i < 2; i++) {                            \
                uint32_t ra = SMEM_SWIZZLE_128B((uint32_t)((wm + i * 16 + lr) * 128 + kk * 32 + kh * 16)); \
                ldm_x4(aH[i], AH_OFF(buf) + ra);                                       \
                ldm_x4(aL[i], AL_OFF(buf) + ra);                                       \
            }                                                                          \
            _Pragma("unroll") for (int j = 0; j < 4; j++) {                            \
                uint32_t bfr[4];                                                       \
                ldm_x4(bfr, BH_OFF(buf) +                                              \
                       SMEM_SWIZZLE_128B((uint32_t)((wn + j * 16 + lr) * 128 + kk * 32 + kh * 16))); \
                uint32_t blo[2] = { bfr[0], bfr[2] };                                  \
                uint32_t bhi[2] = { bfr[1], bfr[3] };                                  \
                _Pragma("unroll") for (int i = 0; i < 2; i++) {                        \
                    mma_f16(acc[i][2 * j],     aH[i], blo);                            \
                    mma_f16(acc[i][2 * j + 1], aH[i], bhi);                            \
                    mma_f16(acc[i][2 * j],     aL[i], blo);                            \
                    mma_f16(acc[i][2 * j + 1], aL[i], bhi);                            \
                }                                                                      \
            }                                                                          \
        }                                                                              \
        __syncthreads();                                                               \
    }

// ---------------------------------------------------------------------------
// Fused Q/K/V projection. blockIdx.z: 0=Q (norm+rope, hi+lo), 1=K (norm+rope, hi),
// 2=V (transposed fp16 [b,h,d,s] via smem staging).
// Q carries 0.125 * log2(e) so flash can use exp2f directly.
// ---------------------------------------------------------------------------
__global__ void __launch_bounds__(256, 2) proj_qkv(
    const __half* __restrict__ Ah, const __half* __restrict__ Al,
    const __half* __restrict__ Wq, const __half* __restrict__ Wk, const __half* __restrict__ Wv,
    __half* __restrict__ QbH, __half* __restrict__ QbL, __half* __restrict__ KbH,
    __half* __restrict__ Vt,
    const float* __restrict__ qscale, const float* __restrict__ kscale,
    const float* __restrict__ cosT, const float* __restrict__ sinT)
{
    extern __shared__ char smem[];
    uint32_t raw = smem_to_u32(smem);
    uint32_t base = (raw + 1023u) & ~1023u;

    const int tid = threadIdx.x;
    const int lane = tid & 31, wid = tid >> 5;
    const int wm = (wid >> 1) * 32;
    const int wn = (wid & 1) * 64;
    const int bm = blockIdx.y * 128;
    const int bn = blockIdx.x * 128;
    const int zb = blockIdx.z;
    const __half* Bh = (zb == 0) ? Wq : (zb == 1) ? Wk : Wv;

    GEMM_MAINLOOP(Ah, Al, Bh)

    const int rl = lane >> 2, cl = (lane & 3) * 2;

    if (zb == 2) {
        __half* st = reinterpret_cast<__half*>(smem + (base - raw));
#pragma unroll
        for (int i = 0; i < 2; i++)
#pragma unroll
            for (int j = 0; j < 8; j++) {
                int row0 = wm + i * 16 + rl;
                int col  = wn + j * 8 + cl;
                st[(col)     * 136 + row0]     = __float2half_rn(acc[i][j][0]);
                st[(col + 1) * 136 + row0]     = __float2half_rn(acc[i][j][1]);
                st[(col)     * 136 + row0 + 8] = __float2half_rn(acc[i][j][2]);
                st[(col + 1) * 136 + row0 + 8] = __float2half_rn(acc[i][j][3]);
            }
        __syncthreads();
        int b = bm >> 11, s0 = bm & (SEQ - 1);
        int hbase = bn >> 6;
        for (int t = tid; t < 2048; t += 256) {
            int col = t >> 4, sc = t & 15;
            uint4 v = *reinterpret_cast<uint4*>(&st[col * 136 + sc * 8]);
            int head = hbase + (col >> 6), d = col & 63;
            *reinterpret_cast<uint4*>(
                Vt + ((size_t)(b * NH + head) * HD + d) * SEQ + s0 + sc * 8) = v;
        }
    } else {
        const int head = (bn >> 6) + (wn >> 6);
        // Q: fold softmax scale AND log2(e): 0.125 * 1.4426950408889634
        const float postmul = (zb == 0) ? 0.18033688011112042f : 1.0f;
        const float* sc = (zb == 0) ? qscale : kscale;
        const bool wantLo = (zb == 0);
#pragma unroll
        for (int i = 0; i < 2; i++) {
#pragma unroll
            for (int half = 0; half < 2; half++) {
                int row = bm + wm + i * 16 + rl + half * 8;
                int b = row >> 11, s = row & (SEQ - 1);
                float ss = 0.f;
#pragma unroll
                for (int j = 0; j < 8; j++) {
                    float a0 = acc[i][j][2 * half], a1 = acc[i][j][2 * half + 1];
                    ss += a0 * a0 + a1 * a1;
                }
                ss += __shfl_xor_sync(0xffffffffu, ss, 1);
                ss += __shfl_xor_sync(0xffffffffu, ss, 2);
                float r = rsqrtf(ss * (1.0f / 64.0f) + EPSV);
                int z = b * NH + head;
                size_t rowoff = ((size_t)z * SEQ + s) * HD;
#pragma unroll
                for (int j = 0; j < 8; j++) {
                    int ch = j * 8 + cl;
                    int f = ch >> 1;
                    float c_ = cosT[s * 32 + f];
                    float sn = sinT[s * 32 + f];
                    float tr = acc[i][j][2 * half] * r * sc[ch];
                    float ti = acc[i][j][2 * half + 1] * r * sc[ch + 1];
                    float ox = (tr * c_ - ti * sn) * postmul;
                    float oy = (tr * sn + ti * c_) * postmul;
                    __half2 hp = __floats2half2_rn(ox, oy);
                    if (wantLo) {
                        *(__half2*)(QbH + rowoff + ch) = hp;
                        float2 hf = __half22float2(hp);
                        *(__half2*)(QbL + rowoff + ch) =
                            __floats2half2_rn(ox - hf.x, oy - hf.y);
                    } else {
                        *(__half2*)(KbH + rowoff + ch) = hp;
                    }
                }
            }
        }
    }
}

// ---------------------------------------------------------------------------
// Output projection: attn(split fp16) x Wo(hi) -> fp32 out
// ---------------------------------------------------------------------------
__global__ void __launch_bounds__(256, 2) proj_out(
    const __half* __restrict__ Ah, const __half* __restrict__ Al,
    const __half* __restrict__ Bhw, float* __restrict__ Cf)
{
    extern __shared__ char smem[];
    uint32_t raw = smem_to_u32(smem);
    uint32_t base = (raw + 1023u) & ~1023u;

    const int tid = threadIdx.x;
    const int lane = tid & 31, wid = tid >> 5;
    const int wm = (wid >> 1) * 32;
    const int wn = (wid & 1) * 64;
    const int bm = blockIdx.y * 128;
    const int bn = blockIdx.x * 128;

    GEMM_MAINLOOP(Ah, Al, Bhw)

    const int rl = lane >> 2, cl = (lane & 3) * 2;
#pragma unroll
    for (int i = 0; i < 2; i++)
#pragma unroll
        for (int j = 0; j < 8; j++) {
            int row0 = bm + wm + i * 16 + rl;
            int col  = bn + wn + j * 8 + cl;
            float2 lo; lo.x = acc[i][j][0]; lo.y = acc[i][j][1];
            float2 hi; hi.x = acc[i][j][2]; hi.y = acc[i][j][3];
            *(float2*)(Cf + (size_t)row0 * DM + col) = lo;
            *(float2*)(Cf + (size_t)(row0 + 8) * DM + col) = hi;
        }
}

// ---------------------------------------------------------------------------
// Fused flash attention with FIXED-MAX softmax (scores provably bounded).
// TRIPLE-buffered K/V tiles, ONE __syncthreads per tile: warps can drift a
// full tile apart, overlapping one warp's exp/pack with another's MMAs.
// WAR safety: iter c writes buf((c+1)%3), last read in iter c-2; the top
// sync of iter c-1 (program-order after iter c-2's reads) protects it.
// Grid: (SEQ/128, NH, BATCH), 256 threads (8 warps x 16 q-rows), 64-key tiles.
// ---------------------------------------------------------------------------
__global__ void __launch_bounds__(256, 2) flash_attn(
    const __half* __restrict__ Qh, const __half* __restrict__ Ql,
    const __half* __restrict__ Kh, const __half* __restrict__ Vth,
    __half* __restrict__ Oh, __half* __restrict__ Ol)
{
    extern __shared__ char smem[];
    uint32_t raw = smem_to_u32(smem);
    uint32_t base = (raw + 1023u) & ~1023u;
    const uint32_t QH_OFF = base, QL_OFF = base + 16384u;
    auto KH_OFF = [&](int buf) { return base + 32768u + (uint32_t)buf * 16384u; };
    auto VH_OFF = [&](int buf) { return KH_OFF(buf) + 8192u; };

    const int tid = threadIdx.x;
    const int lane = tid & 31, wid = tid >> 5;
    const int lr = lane & 15, kh4 = lane >> 4;
    const int wm = wid * 16;

    const int z = blockIdx.z * NH + blockIdx.y;
    const int b = blockIdx.z, h = blockIdx.y;
    const int q0 = blockIdx.x * 128;

    const __half* qh = Qh + ((size_t)z * SEQ + q0) * HD;
    const __half* ql = Ql + ((size_t)z * SEQ + q0) * HD;
    const __half* kbh = Kh + (size_t)z * SEQ * HD;
    const __half* vth = Vth + (size_t)z * HD * SEQ;

    // Q (hi+lo) load: joins tile-0's cp.async group
    for (int idx = tid; idx < 2048; idx += 256) {
        bool isH = idx < 1024;
        int li = idx & 1023;
        int row = li >> 3, seg = li & 7;
        const __half* src = (isH ? qh : ql) + (size_t)row * HD + seg * 8;
        uint32_t dst = (isH ? QH_OFF : QL_OFF) + SMEM_SWIZZLE_128B((uint32_t)(row * 128 + seg * 16));
        CP_ASYNC16(dst, src);
    }

    auto load_tile = [&](int kt, int buf) {
        for (int idx = tid; idx < 512; idx += 256) {
            int row = idx >> 3, seg = idx & 7;
            CP_ASYNC16(KH_OFF(buf) + SMEM_SWIZZLE_128B((uint32_t)(row * 128 + seg * 16)),
                       kbh + (size_t)(kt + row) * HD + seg * 8);
        }
        for (int idx = tid; idx < 512; idx += 256) {
            int d = idx >> 3, seg = idx & 7;
            CP_ASYNC16(VH_OFF(buf) + SMEM_SWIZZLE_128B((uint32_t)(d * 128 + seg * 16)),
                       vth + (size_t)d * SEQ + kt + seg * 8);
        }
        CP_COMMIT();
    };

    load_tile(0, 0);

    float l_i[2] = { 0.f, 0.f };
    float oacc[8][4];
#pragma unroll
    for (int j = 0; j < 8; j++)
#pragma unroll
        for (int q = 0; q < 4; q++) oacc[j][q] = 0.f;

    const int NT = SEQ / 64;
    int cur = 0, nxt = 1;                 // rotating mod-3 buffer indices
    for (int c = 0; c < NT; c++) {
        if (c + 1 < NT) { load_tile((c + 1) * 64, nxt); CP_WAIT1(); }
        else            { CP_WAIT0(); }
        __syncthreads();                   // single sync per tile

        // ---- S = Q K^T (2-pass): per-warp 16 x 64, log2-domain scores
        float sacc[8][4];
#pragma unroll
        for (int j = 0; j < 8; j++)
#pragma unroll
            for (int q = 0; q < 4; q++) sacc[j][q] = 0.f;

#pragma unroll
        for (int kk = 0; kk < 4; kk++) {
            uint32_t ra = SMEM_SWIZZLE_128B((uint32_t)((wm + lr) * 128 + kk * 32 + kh4 * 16));
            uint32_t aH[4], aL[4];
            ldm_x4(aH, QH_OFF + ra);
            ldm_x4(aL, QL_OFF + ra);
#pragma unroll
            for (int nf = 0; nf < 4; nf++) {
                uint32_t bh4[4];
                ldm_x4(bh4, KH_OFF(cur) +
                       SMEM_SWIZZLE_128B((uint32_t)((nf * 16 + lr) * 128 + kk * 32 + kh4 * 16)));
                uint32_t blo[2] = { bh4[0], bh4[2] }, bhi[2] = { bh4[1], bh4[3] };
                mma_f16(sacc[2 * nf],     aH, blo);
                mma_f16(sacc[2 * nf + 1], aH, bhi);
                mma_f16(sacc[2 * nf],     aL, blo);
                mma_f16(sacc[2 * nf + 1], aL, bhi);
            }
        }

        // ---- fixed-max softmax: p = 2^s (no max tracking, no rescale)
#pragma unroll
        for (int j = 0; j < 8; j++) {
            sacc[j][0] = exp2f(sacc[j][0]);
            sacc[j][1] = exp2f(sacc[j][1]);
            sacc[j][2] = exp2f(sacc[j][2]);
            sacc[j][3] = exp2f(sacc[j][3]);
            l_i[0] += sacc[j][0] + sacc[j][1];
            l_i[1] += sacc[j][2] + sacc[j][3];
        }

        // ---- O += P V (2-pass; P split in-register)
#pragma unroll
        for (int kk = 0; kk < 4; kk++) {
            float p0 = sacc[2 * kk][0],     p1 = sacc[2 * kk][1];
            float p2 = sacc[2 * kk][2],     p3 = sacc[2 * kk][3];
            float p4 = sacc[2 * kk + 1][0], p5 = sacc[2 * kk + 1][1];
            float p6 = sacc[2 * kk + 1][2], p7 = sacc[2 * kk + 1][3];
            __half2 h01 = __floats2half2_rn(p0, p1);
            __half2 h23 = __floats2half2_rn(p2, p3);
            __half2 h45 = __floats2half2_rn(p4, p5);
            __half2 h67 = __floats2half2_rn(p6, p7);
            uint32_t ah[4] = { h2u(h01), h2u(h23), h2u(h45), h2u(h67) };
            float2 f01 = __half22float2(h01);
            float2 f23 = __half22float2(h23);
            float2 f45 = __half22float2(h45);
            float2 f67 = __half22float2(h67);
            uint32_t alr[4] = {
                h2u(__floats2half2_rn(p0 - f01.x, p1 - f01.y)),
                h2u(__floats2half2_rn(p2 - f23.x, p3 - f23.y)),
                h2u(__floats2half2_rn(p4 - f45.x, p5 - f45.y)),
                h2u(__floats2half2_rn(p6 - f67.x, p7 - f67.y))
            };
#pragma unroll
            for (int nfp = 0; nfp < 4; nfp++) {
                uint32_t bh4[4];
                ldm_x4(bh4, VH_OFF(cur) +
                       SMEM_SWIZZLE_128B((uint32_t)((nfp * 16 + lr) * 128 + kk * 32 + kh4 * 16)));
                uint32_t blo[2] = { bh4[0], bh4[2] }, bhi[2] = { bh4[1], bh4[3] };
                mma_f16(oacc[2 * nfp],     ah, blo);
                mma_f16(oacc[2 * nfp + 1], ah, bhi);
                mma_f16(oacc[2 * nfp],     alr, blo);
                mma_f16(oacc[2 * nfp + 1], alr, bhi);
            }
        }
        // no bottom sync: triple buffer makes the WAR hazard one sync-epoch away
        cur = (cur == 2) ? 0 : cur + 1;
        nxt = (nxt == 2) ? 0 : nxt + 1;
    }

    // ---- one deferred row-sum reduction (4-lane groups), then normalize
#pragma unroll
    for (int mk = 1; mk <= 2; mk <<= 1) {
        l_i[0] += __shfl_xor_sync(0xffffffffu, l_i[0], mk);
        l_i[1] += __shfl_xor_sync(0xffffffffu, l_i[1], mk);
    }
    float inv0 = 1.0f / l_i[0], inv1 = 1.0f / l_i[1];
    int row0 = q0 + wm + (lane >> 2);
    int colb = h * HD + (lane & 3) * 2;
#pragma unroll
    for (int j = 0; j < 8; j++) {
        float x0 = oacc[j][0] * inv0, x1 = oacc[j][1] * inv0;
        float x2 = oacc[j][2] * inv1, x3 = oacc[j][3] * inv1;
        size_t off0 = ((size_t)(b * SEQ + row0)) * DM + colb + j * 8;
        size_t off1 = ((size_t)(b * SEQ + row0 + 8)) * DM + colb + j * 8;
        __half2 hp0 = __floats2half2_rn(x0, x1);
        __half2 hp1 = __floats2half2_rn(x2, x3);
        *(__half2*)(Oh + off0) = hp0;
        *(__half2*)(Oh + off1) = hp1;
        float2 f0 = __half22float2(hp0);
        float2 f1 = __half22float2(hp1);
        *(__half2*)(Ol + off0) = __floats2half2_rn(x0 - f0.x, x1 - f0.y);
        *(__half2*)(Ol + off1) = __floats2half2_rn(x2 - f1.x, x3 - f1.y);
    }
}

// ---------------------------------------------------------------------------
extern "C" void kernel_launch(void* const* d_in, const int* in_sizes, int n_in,
                              void* d_out, int out_size)
{
    const float* x        = (const float*)d_in[0];
    const float* wq       = (const float*)d_in[1];
    const float* wk       = (const float*)d_in[2];
    const float* wv       = (const float*)d_in[3];
    const float* wo       = (const float*)d_in[4];
    const float* q_scale  = (const float*)d_in[5];
    const float* k_scale  = (const float*)d_in[6];
    const float* rope_cos = (const float*)d_in[7];
    const float* rope_sin = (const float*)d_in[8];
    float* out = (float*)d_out;

    __half *xh, *xl, *wqh, *wkh, *wvh, *woh;
    __half *qbh, *qbl, *kbh, *vth, *ath, *atl;
    cudaGetSymbolAddress((void**)&xh, g_xh);     cudaGetSymbolAddress((void**)&xl, g_xl);
    cudaGetSymbolAddress((void**)&wqh, g_wqh);   cudaGetSymbolAddress((void**)&wkh, g_wkh);
    cudaGetSymbolAddress((void**)&wvh, g_wvh);   cudaGetSymbolAddress((void**)&woh, g_woh);
    cudaGetSymbolAddress((void**)&qbh, g_qbh);   cudaGetSymbolAddress((void**)&qbl, g_qbl);
    cudaGetSymbolAddress((void**)&kbh, g_kbh);
    cudaGetSymbolAddress((void**)&vth, g_vth);
    cudaGetSymbolAddress((void**)&ath, g_ath);   cudaGetSymbolAddress((void**)&atl, g_atl);

    const int SMG = 1024 + 2 * 49152;            // 99328
    const int SMF = 1024 + 32768 + 3 * 16384;    // 82944 (triple-buffered K/V)
    cudaFuncSetAttribute(proj_qkv, cudaFuncAttributeMaxDynamicSharedMemorySize, SMG);
    cudaFuncSetAttribute(proj_out, cudaFuncAttributeMaxDynamicSharedMemorySize, SMG);
    cudaFuncSetAttribute(flash_attn, cudaFuncAttributeMaxDynamicSharedMemorySize, SMF);

    const int NXE = BATCH * SEQ * DM;
    const int NWE = DM * DM;

    split_f32h<<<(NXE + 255) / 256, 256>>>(x, xh, xl, NXE);
    conv_weights<<<(4 * NWE) / 256, 256>>>(wq, wk, wv, wo, wqh, wkh, wvh, woh);

    proj_qkv<<<dim3(DM / 128, (BATCH * SEQ) / 128, 3), 256, SMG>>>(
        xh, xl, wqh, wkh, wvh, qbh, qbl, kbh, vth,
        q_scale, k_scale, rope_cos, rope_sin);

    flash_attn<<<dim3(SEQ / 128, NH, BATCH), 256, SMF>>>(qbh, qbl, kbh, vth, ath, atl);

    proj_out<<<dim3(DM / 128, (BATCH * SEQ) / 128), 256, SMG>>>(ath, atl, woh, out);
}

// round 13
// speedup vs baseline: 1.5428x; 1.5428x over previous
#include <cuda_runtime.h>
#include <cuda_fp16.h>
#include <cstdint>
#include <math.h>

#define BATCH 2
#define SEQ 2048
#define DM 1024
#define NH 16
#define HD 64
#define EPSV 1e-6f

// ---------------------------------------------------------------------------
// Scratch (__device__ globals: allocation-free rule)
// ---------------------------------------------------------------------------
__device__ __half g_xh[BATCH * SEQ * DM];
__device__ __half g_xl[BATCH * SEQ * DM];
__device__ __half g_wqh[DM * DM], g_wkh[DM * DM], g_wvh[DM * DM], g_woh[DM * DM];
__device__ __half g_qbh[BATCH * NH * SEQ * HD], g_qbl[BATCH * NH * SEQ * HD];
__device__ __half g_kbh[BATCH * NH * SEQ * HD];
__device__ __half g_vth[BATCH * NH * HD * SEQ];      // [b,h,d,s] fp16
__device__ __half g_ath[BATCH * SEQ * DM], g_atl[BATCH * SEQ * DM];

// ---------------------------------------------------------------------------
// Helpers (non-'a' instructions only: legal under compute_103)
// ---------------------------------------------------------------------------
__device__ __forceinline__ uint32_t smem_to_u32(const void* p) {
    uint32_t a;
    asm("{ .reg .u64 t; cvta.to.shared.u64 t, %1; cvt.u32.u64 %0, t; }" : "=r"(a) : "l"(p));
    return a;
}
#define SMEM_SWIZZLE_128B(o) ((o) ^ (((o) >> 3) & 0x70))

#define CP_ASYNC16(dst, src) \
    asm volatile("cp.async.cg.shared.global [%0], [%1], 16;" :: "r"(dst), "l"(src))
#define CP_COMMIT() asm volatile("cp.async.commit_group;" ::: "memory")
#define CP_WAIT0()  asm volatile("cp.async.wait_group 0;" ::: "memory")
#define CP_WAIT1()  asm volatile("cp.async.wait_group 1;" ::: "memory")

__device__ __forceinline__ void ldm_x4(uint32_t* r, uint32_t addr) {
    asm volatile("ldmatrix.sync.aligned.m8n8.x4.shared.b16 {%0,%1,%2,%3}, [%4];"
                 : "=r"(r[0]), "=r"(r[1]), "=r"(r[2]), "=r"(r[3]) : "r"(addr));
}
__device__ __forceinline__ void mma_f16(float* d, const uint32_t* a, const uint32_t* b) {
    asm volatile("mma.sync.aligned.m16n8k16.row.col.f32.f16.f16.f32 "
        "{%0,%1,%2,%3}, {%4,%5,%6,%7}, {%8,%9}, {%0,%1,%2,%3};"
        : "+f"(d[0]), "+f"(d[1]), "+f"(d[2]), "+f"(d[3])
        : "r"(a[0]), "r"(a[1]), "r"(a[2]), "r"(a[3]), "r"(b[0]), "r"(b[1]));
}
__device__ __forceinline__ uint32_t h2u(__half2 h) { return *reinterpret_cast<uint32_t*>(&h); }

// ---------------------------------------------------------------------------
__global__ void split_f32h(const float* __restrict__ in, __half* __restrict__ h,
                           __half* __restrict__ l, int n)
{
    int i = blockIdx.x * blockDim.x + threadIdx.x;
    if (i < n) {
        float x = in[i];
        __half hi = __float2half_rn(x);
        h[i] = hi;
        l[i] = __float2half_rn(x - __half2float(hi));
    }
}

__global__ void conv_weights(const float* __restrict__ wq, const float* __restrict__ wk,
                             const float* __restrict__ wv, const float* __restrict__ wo,
                             __half* __restrict__ oq, __half* __restrict__ ok,
                             __half* __restrict__ ov, __half* __restrict__ oo)
{
    int i = blockIdx.x * blockDim.x + threadIdx.x;
    int sel = i >> 20, li = i & ((1 << 20) - 1);
    const float* src = sel == 0 ? wq : sel == 1 ? wk : sel == 2 ? wv : wo;
    __half* dst = sel == 0 ? oq : sel == 1 ? ok : sel == 2 ? ov : oo;
    dst[li] = __float2half_rn(src[li]);
}

// ---------------------------------------------------------------------------
// Shared GEMM mainloop: 128x128 tile, BK=64, 2-pass split A(hi+lo) x B(hi).
// ---------------------------------------------------------------------------
#define GEMM_MAINLOOP(Ahp, Alp, Bhp)                                                   \
    auto AH_OFF = [&](int buf) { return base + (uint32_t)buf * 49152u; };              \
    auto AL_OFF = [&](int buf) { return AH_OFF(buf) + 16384u; };                       \
    auto BH_OFF = [&](int buf) { return AH_OFF(buf) + 32768u; };                       \
    float acc[2][8][4];                                                                \
    _Pragma("unroll") for (int i = 0; i < 2; i++)                                      \
        _Pragma("unroll") for (int j = 0; j < 8; j++)                                  \
            _Pragma("unroll") for (int q = 0; q < 4; q++) acc[i][j][q] = 0.f;          \
    auto load_chunk = [&](int c) {                                                     \
        int k0 = c << 6;                                                               \
        int buf = c & 1;                                                               \
        for (int idx = tid; idx < 3072; idx += 256) {                                  \
            int sel = idx >> 10;                                                       \
            int li = idx & 1023;                                                       \
            int row = li >> 3, seg = li & 7;                                           \
            const __half* src;                                                         \
            uint32_t dstb;                                                             \
            if (sel == 0)      { src = Ahp + (size_t)(bm + row) * DM + k0; dstb = AH_OFF(buf); } \
            else if (sel == 1) { src = Alp + (size_t)(bm + row) * DM + k0; dstb = AL_OFF(buf); } \
            else               { src = Bhp + (size_t)(bn + row) * DM + k0; dstb = BH_OFF(buf); } \
            CP_ASYNC16(dstb + SMEM_SWIZZLE_128B((uint32_t)(row * 128 + seg * 16)), src + seg * 8); \
        }                                                                              \
        CP_COMMIT();                                                                   \
    };                                                                                 \
    load_chunk(0);                                                                     \
    const int lr = lane & 15, kh = lane >> 4;                                          \
    const int kc = DM >> 6;                                                            \
    for (int c = 0; c < kc; c++) {                                                     \
        if (c + 1 < kc) { load_chunk(c + 1); CP_WAIT1(); }                             \
        else            { CP_WAIT0(); }                                                \
        __syncthreads();                                                               \
        int buf = c & 1;                                                               \
        _Pragma("unroll") for (int kk = 0; kk < 4; kk++) {                             \
            uint32_t aH[2][4], aL[2][4];                                               \
            _Pragma("unroll") for (int i = 0; i < 2; i++) {                            \
                uint32_t ra = SMEM_SWIZZLE_128B((uint32_t)((wm + i * 16 + lr) * 128 + kk * 32 + kh * 16)); \
                ldm_x4(aH[i], AH_OFF(buf) + ra);                                       \
                ldm_x4(aL[i], AL_OFF(buf) + ra);                                       \
            }                                                                          \
            _Pragma("unroll") for (int j = 0; j < 4; j++) {                            \
                uint32_t bfr[4];                                                       \
                ldm_x4(bfr, BH_OFF(buf) +                                              \
                       SMEM_SWIZZLE_128B((uint32_t)((wn + j * 16 + lr) * 128 + kk * 32 + kh * 16))); \
                uint32_t blo[2] = { bfr[0], bfr[2] };                                  \
                uint32_t bhi[2] = { bfr[1], bfr[3] };                                  \
                _Pragma("unroll") for (int i = 0; i < 2; i++) {                        \
                    mma_f16(acc[i][2 * j],     aH[i], blo);                            \
                    mma_f16(acc[i][2 * j + 1], aH[i], bhi);                            \
                    mma_f16(acc[i][2 * j],     aL[i], blo);                            \
                    mma_f16(acc[i][2 * j + 1], aL[i], bhi);                            \
                }                                                                      \
            }                                                                          \
        }                                                                              \
        __syncthreads();                                                               \
    }

// ---------------------------------------------------------------------------
// Fused Q/K/V projection. blockIdx.z: 0=Q (norm+rope, hi+lo), 1=K (norm+rope, hi),
// 2=V (transposed fp16 [b,h,d,s] via smem staging).
// Q carries 0.125 * log2(e) so flash can use exp2f directly.
// ---------------------------------------------------------------------------
__global__ void __launch_bounds__(256, 2) proj_qkv(
    const __half* __restrict__ Ah, const __half* __restrict__ Al,
    const __half* __restrict__ Wq, const __half* __restrict__ Wk, const __half* __restrict__ Wv,
    __half* __restrict__ QbH, __half* __restrict__ QbL, __half* __restrict__ KbH,
    __half* __restrict__ Vt,
    const float* __restrict__ qscale, const float* __restrict__ kscale,
    const float* __restrict__ cosT, const float* __restrict__ sinT)
{
    extern __shared__ char smem[];
    uint32_t raw = smem_to_u32(smem);
    uint32_t base = (raw + 1023u) & ~1023u;

    const int tid = threadIdx.x;
    const int lane = tid & 31, wid = tid >> 5;
    const int wm = (wid >> 1) * 32;
    const int wn = (wid & 1) * 64;
    const int bm = blockIdx.y * 128;
    const int bn = blockIdx.x * 128;
    const int zb = blockIdx.z;
    const __half* Bh = (zb == 0) ? Wq : (zb == 1) ? Wk : Wv;

    GEMM_MAINLOOP(Ah, Al, Bh)

    const int rl = lane >> 2, cl = (lane & 3) * 2;

    if (zb == 2) {
        __half* st = reinterpret_cast<__half*>(smem + (base - raw));
#pragma unroll
        for (int i = 0; i < 2; i++)
#pragma unroll
            for (int j = 0; j < 8; j++) {
                int row0 = wm + i * 16 + rl;
                int col  = wn + j * 8 + cl;
                st[(col)     * 136 + row0]     = __float2half_rn(acc[i][j][0]);
                st[(col + 1) * 136 + row0]     = __float2half_rn(acc[i][j][1]);
                st[(col)     * 136 + row0 + 8] = __float2half_rn(acc[i][j][2]);
                st[(col + 1) * 136 + row0 + 8] = __float2half_rn(acc[i][j][3]);
            }
        __syncthreads();
        int b = bm >> 11, s0 = bm & (SEQ - 1);
        int hbase = bn >> 6;
        for (int t = tid; t < 2048; t += 256) {
            int col = t >> 4, sc = t & 15;
            uint4 v = *reinterpret_cast<uint4*>(&st[col * 136 + sc * 8]);
            int head = hbase + (col >> 6), d = col & 63;
            *reinterpret_cast<uint4*>(
                Vt + ((size_t)(b * NH + head) * HD + d) * SEQ + s0 + sc * 8) = v;
        }
    } else {
        const int head = (bn >> 6) + (wn >> 6);
        // Q: fold softmax scale AND log2(e): 0.125 * 1.4426950408889634
        const float postmul = (zb == 0) ? 0.18033688011112042f : 1.0f;
        const float* sc = (zb == 0) ? qscale : kscale;
        const bool wantLo = (zb == 0);
#pragma unroll
        for (int i = 0; i < 2; i++) {
#pragma unroll
            for (int half = 0; half < 2; half++) {
                int row = bm + wm + i * 16 + rl + half * 8;
                int b = row >> 11, s = row & (SEQ - 1);
                float ss = 0.f;
#pragma unroll
                for (int j = 0; j < 8; j++) {
                    float a0 = acc[i][j][2 * half], a1 = acc[i][j][2 * half + 1];
                    ss += a0 * a0 + a1 * a1;
                }
                ss += __shfl_xor_sync(0xffffffffu, ss, 1);
                ss += __shfl_xor_sync(0xffffffffu, ss, 2);
                float r = rsqrtf(ss * (1.0f / 64.0f) + EPSV);
                int z = b * NH + head;
                size_t rowoff = ((size_t)z * SEQ + s) * HD;
#pragma unroll
                for (int j = 0; j < 8; j++) {
                    int ch = j * 8 + cl;
                    int f = ch >> 1;
                    float c_ = cosT[s * 32 + f];
                    float sn = sinT[s * 32 + f];
                    float tr = acc[i][j][2 * half] * r * sc[ch];
                    float ti = acc[i][j][2 * half + 1] * r * sc[ch + 1];
                    float ox = (tr * c_ - ti * sn) * postmul;
                    float oy = (tr * sn + ti * c_) * postmul;
                    __half2 hp = __floats2half2_rn(ox, oy);
                    if (wantLo) {
                        *(__half2*)(QbH + rowoff + ch) = hp;
                        float2 hf = __half22float2(hp);
                        *(__half2*)(QbL + rowoff + ch) =
                            __floats2half2_rn(ox - hf.x, oy - hf.y);
                    } else {
                        *(__half2*)(KbH + rowoff + ch) = hp;
                    }
                }
            }
        }
    }
}

// ---------------------------------------------------------------------------
// Output projection: attn(split fp16) x Wo(hi) -> fp32 out
// ---------------------------------------------------------------------------
__global__ void __launch_bounds__(256, 2) proj_out(
    const __half* __restrict__ Ah, const __half* __restrict__ Al,
    const __half* __restrict__ Bhw, float* __restrict__ Cf)
{
    extern __shared__ char smem[];
    uint32_t raw = smem_to_u32(smem);
    uint32_t base = (raw + 1023u) & ~1023u;

    const int tid = threadIdx.x;
    const int lane = tid & 31, wid = tid >> 5;
    const int wm = (wid >> 1) * 32;
    const int wn = (wid & 1) * 64;
    const int bm = blockIdx.y * 128;
    const int bn = blockIdx.x * 128;

    GEMM_MAINLOOP(Ah, Al, Bhw)

    const int rl = lane >> 2, cl = (lane & 3) * 2;
#pragma unroll
    for (int i = 0; i < 2; i++)
#pragma unroll
        for (int j = 0; j < 8; j++) {
            int row0 = bm + wm + i * 16 + rl;
            int col  = bn + wn + j * 8 + cl;
            float2 lo; lo.x = acc[i][j][0]; lo.y = acc[i][j][1];
            float2 hi; hi.x = acc[i][j][2]; hi.y = acc[i][j][3];
            *(float2*)(Cf + (size_t)row0 * DM + col) = lo;
            *(float2*)(Cf + (size_t)(row0 + 8) * DM + col) = hi;
        }
}

// ---------------------------------------------------------------------------
// Fused flash attention with FIXED-MAX softmax (R10 design: double buffer,
// two syncs per tile) + hoisted cp.async addressing (pointers advanced by
// constant strides; smem dst constants precomputed per buffer).
// Grid: (SEQ/128, NH, BATCH), 256 threads (8 warps x 16 q-rows), 64-key tiles.
// ---------------------------------------------------------------------------
__global__ void __launch_bounds__(256, 2) flash_attn(
    const __half* __restrict__ Qh, const __half* __restrict__ Ql,
    const __half* __restrict__ Kh, const __half* __restrict__ Vth,
    __half* __restrict__ Oh, __half* __restrict__ Ol)
{
    extern __shared__ char smem[];
    uint32_t raw = smem_to_u32(smem);
    uint32_t base = (raw + 1023u) & ~1023u;
    const uint32_t QH_OFF = base, QL_OFF = base + 16384u;
    auto KH_OFF = [&](int buf) { return base + 32768u + (uint32_t)buf * 16384u; };
    auto VH_OFF = [&](int buf) { return KH_OFF(buf) + 8192u; };

    const int tid = threadIdx.x;
    const int lane = tid & 31, wid = tid >> 5;
    const int lr = lane & 15, kh4 = lane >> 4;
    const int wm = wid * 16;

    const int z = blockIdx.z * NH + blockIdx.y;
    const int b = blockIdx.z, h = blockIdx.y;
    const int q0 = blockIdx.x * 128;

    const __half* qh = Qh + ((size_t)z * SEQ + q0) * HD;
    const __half* ql = Ql + ((size_t)z * SEQ + q0) * HD;

    // Q (hi+lo) load: joins tile-0's cp.async group
    for (int idx = tid; idx < 2048; idx += 256) {
        bool isH = idx < 1024;
        int li = idx & 1023;
        int row = li >> 3, seg = li & 7;
        const __half* src = (isH ? qh : ql) + (size_t)row * HD + seg * 8;
        uint32_t dst = (isH ? QH_OFF : QL_OFF) + SMEM_SWIZZLE_128B((uint32_t)(row * 128 + seg * 16));
        CP_ASYNC16(dst, src);
    }

    // ---- hoisted K/V load addressing: per-thread src pointers + dst consts
    // K strip: idx in {tid, tid+256}; row = idx>>3, seg = idx&7
    // V strip: idx in {tid, tid+256}; d = idx>>3, seg = idx&7
    const int i0 = tid, i1 = tid + 256;
    const __half* kS0 = Kh + (size_t)z * SEQ * HD + (i0 >> 3) * HD + (i0 & 7) * 8;
    const __half* kS1 = Kh + (size_t)z * SEQ * HD + (i1 >> 3) * HD + (i1 & 7) * 8;
    const __half* vS0 = Vth + (size_t)z * HD * SEQ + (size_t)(i0 >> 3) * SEQ + (i0 & 7) * 8;
    const __half* vS1 = Vth + (size_t)z * HD * SEQ + (size_t)(i1 >> 3) * SEQ + (i1 & 7) * 8;
    const uint32_t kOffs0 = SMEM_SWIZZLE_128B((uint32_t)((i0 >> 3) * 128 + (i0 & 7) * 16));
    const uint32_t kOffs1 = SMEM_SWIZZLE_128B((uint32_t)((i1 >> 3) * 128 + (i1 & 7) * 16));
    const uint32_t kD0[2] = { KH_OFF(0) + kOffs0, KH_OFF(1) + kOffs0 };
    const uint32_t kD1[2] = { KH_OFF(0) + kOffs1, KH_OFF(1) + kOffs1 };
    const uint32_t vD0[2] = { VH_OFF(0) + kOffs0, VH_OFF(1) + kOffs0 };
    const uint32_t vD1[2] = { VH_OFF(0) + kOffs1, VH_OFF(1) + kOffs1 };

    auto load_tile = [&](int buf) {
        CP_ASYNC16(kD0[buf], kS0);
        CP_ASYNC16(kD1[buf], kS1);
        CP_ASYNC16(vD0[buf], vS0);
        CP_ASYNC16(vD1[buf], vS1);
        CP_COMMIT();
        kS0 += 64 * HD; kS1 += 64 * HD;   // next 64 keys
        vS0 += 64;      vS1 += 64;        // next 64 s-positions
    };

    load_tile(0);

    float l_i[2] = { 0.f, 0.f };
    float oacc[8][4];
#pragma unroll
    for (int j = 0; j < 8; j++)
#pragma unroll
        for (int q = 0; q < 4; q++) oacc[j][q] = 0.f;

    const int NT = SEQ / 64;
    for (int c = 0; c < NT; c++) {
        int buf = c & 1;
        if (c + 1 < NT) { load_tile(buf ^ 1); CP_WAIT1(); }
        else            { CP_WAIT0(); }
        __syncthreads();

        // ---- S = Q K^T (2-pass): per-warp 16 x 64, log2-domain scores
        float sacc[8][4];
#pragma unroll
        for (int j = 0; j < 8; j++)
#pragma unroll
            for (int q = 0; q < 4; q++) sacc[j][q] = 0.f;

#pragma unroll
        for (int kk = 0; kk < 4; kk++) {
            uint32_t ra = SMEM_SWIZZLE_128B((uint32_t)((wm + lr) * 128 + kk * 32 + kh4 * 16));
            uint32_t aH[4], aL[4];
            ldm_x4(aH, QH_OFF + ra);
            ldm_x4(aL, QL_OFF + ra);
#pragma unroll
            for (int nf = 0; nf < 4; nf++) {
                uint32_t bh4[4];
                ldm_x4(bh4, KH_OFF(buf) +
                       SMEM_SWIZZLE_128B((uint32_t)((nf * 16 + lr) * 128 + kk * 32 + kh4 * 16)));
                uint32_t blo[2] = { bh4[0], bh4[2] }, bhi[2] = { bh4[1], bh4[3] };
                mma_f16(sacc[2 * nf],     aH, blo);
                mma_f16(sacc[2 * nf + 1], aH, bhi);
                mma_f16(sacc[2 * nf],     aL, blo);
                mma_f16(sacc[2 * nf + 1], aL, bhi);
            }
        }

        // ---- fixed-max softmax: p = 2^s (no max tracking, no rescale)
#pragma unroll
        for (int j = 0; j < 8; j++) {
            sacc[j][0] = exp2f(sacc[j][0]);
            sacc[j][1] = exp2f(sacc[j][1]);
            sacc[j][2] = exp2f(sacc[j][2]);
            sacc[j][3] = exp2f(sacc[j][3]);
            l_i[0] += sacc[j][0] + sacc[j][1];
            l_i[1] += sacc[j][2] + sacc[j][3];
        }

        // ---- O += P V (2-pass; P split in-register)
#pragma unroll
        for (int kk = 0; kk < 4; kk++) {
            float p0 = sacc[2 * kk][0],     p1 = sacc[2 * kk][1];
            float p2 = sacc[2 * kk][2],     p3 = sacc[2 * kk][3];
            float p4 = sacc[2 * kk + 1][0], p5 = sacc[2 * kk + 1][1];
            float p6 = sacc[2 * kk + 1][2], p7 = sacc[2 * kk + 1][3];
            __half2 h01 = __floats2half2_rn(p0, p1);
            __half2 h23 = __floats2half2_rn(p2, p3);
            __half2 h45 = __floats2half2_rn(p4, p5);
            __half2 h67 = __floats2half2_rn(p6, p7);
            uint32_t ah[4] = { h2u(h01), h2u(h23), h2u(h45), h2u(h67) };
            float2 f01 = __half22float2(h01);
            float2 f23 = __half22float2(h23);
            float2 f45 = __half22float2(h45);
            float2 f67 = __half22float2(h67);
            uint32_t alr[4] = {
                h2u(__floats2half2_rn(p0 - f01.x, p1 - f01.y)),
                h2u(__floats2half2_rn(p2 - f23.x, p3 - f23.y)),
                h2u(__floats2half2_rn(p4 - f45.x, p5 - f45.y)),
                h2u(__floats2half2_rn(p6 - f67.x, p7 - f67.y))
            };
#pragma unroll
            for (int nfp = 0; nfp < 4; nfp++) {
                uint32_t bh4[4];
                ldm_x4(bh4, VH_OFF(buf) +
                       SMEM_SWIZZLE_128B((uint32_t)((nfp * 16 + lr) * 128 + kk * 32 + kh4 * 16)));
                uint32_t blo[2] = { bh4[0], bh4[2] }, bhi[2] = { bh4[1], bh4[3] };
                mma_f16(oacc[2 * nfp],     ah, blo);
                mma_f16(oacc[2 * nfp + 1], ah, bhi);
                mma_f16(oacc[2 * nfp],     alr, blo);
                mma_f16(oacc[2 * nfp + 1], alr, bhi);
            }
        }
        __syncthreads();
    }

    // ---- one deferred row-sum reduction (4-lane groups), then normalize
#pragma unroll
    for (int mk = 1; mk <= 2; mk <<= 1) {
        l_i[0] += __shfl_xor_sync(0xffffffffu, l_i[0], mk);
        l_i[1] += __shfl_xor_sync(0xffffffffu, l_i[1], mk);
    }
    float inv0 = 1.0f / l_i[0], inv1 = 1.0f / l_i[1];
    int row0 = q0 + wm + (lane >> 2);
    int colb = h * HD + (lane & 3) * 2;
#pragma unroll
    for (int j = 0; j < 8; j++) {
        float x0 = oacc[j][0] * inv0, x1 = oacc[j][1] * inv0;
        float x2 = oacc[j][2] * inv1, x3 = oacc[j][3] * inv1;
        size_t off0 = ((size_t)(b * SEQ + row0)) * DM + colb + j * 8;
        size_t off1 = ((size_t)(b * SEQ + row0 + 8)) * DM + colb + j * 8;
        __half2 hp0 = __floats2half2_rn(x0, x1);
        __half2 hp1 = __floats2half2_rn(x2, x3);
        *(__half2*)(Oh + off0) = hp0;
        *(__half2*)(Oh + off1) = hp1;
        float2 f0 = __half22float2(hp0);
        float2 f1 = __half22float2(hp1);
        *(__half2*)(Ol + off0) = __floats2half2_rn(x0 - f0.x, x1 - f0.y);
        *(__half2*)(Ol + off1) = __floats2half2_rn(x2 - f1.x, x3 - f1.y);
    }
}

// ---------------------------------------------------------------------------
extern "C" void kernel_launch(void* const* d_in, const int* in_sizes, int n_in,
                              void* d_out, int out_size)
{
    const float* x        = (const float*)d_in[0];
    const float* wq       = (const float*)d_in[1];
    const float* wk       = (const float*)d_in[2];
    const float* wv       = (const float*)d_in[3];
    const float* wo       = (const float*)d_in[4];
    const float* q_scale  = (const float*)d_in[5];
    const float* k_scale  = (const float*)d_in[6];
    const float* rope_cos = (const float*)d_in[7];
    const float* rope_sin = (const float*)d_in[8];
    float* out = (float*)d_out;

    __half *xh, *xl, *wqh, *wkh, *wvh, *woh;
    __half *qbh, *qbl, *kbh, *vth, *ath, *atl;
    cudaGetSymbolAddress((void**)&xh, g_xh);     cudaGetSymbolAddress((void**)&xl, g_xl);
    cudaGetSymbolAddress((void**)&wqh, g_wqh);   cudaGetSymbolAddress((void**)&wkh, g_wkh);
    cudaGetSymbolAddress((void**)&wvh, g_wvh);   cudaGetSymbolAddress((void**)&woh, g_woh);
    cudaGetSymbolAddress((void**)&qbh, g_qbh);   cudaGetSymbolAddress((void**)&qbl, g_qbl);
    cudaGetSymbolAddress((void**)&kbh, g_kbh);
    cudaGetSymbolAddress((void**)&vth, g_vth);
    cudaGetSymbolAddress((void**)&ath, g_ath);   cudaGetSymbolAddress((void**)&atl, g_atl);

    const int SMG = 1024 + 2 * 49152;            // 99328
    const int SMF = 1024 + 32768 + 2 * 16384;    // 66560 (double-buffered K/V)
    cudaFuncSetAttribute(proj_qkv, cudaFuncAttributeMaxDynamicSharedMemorySize, SMG);
    cudaFuncSetAttribute(proj_out, cudaFuncAttributeMaxDynamicSharedMemorySize, SMG);
    cudaFuncSetAttribute(flash_attn, cudaFuncAttributeMaxDynamicSharedMemorySize, SMF);

    const int NXE = BATCH * SEQ * DM;
    const int NWE = DM * DM;

    split_f32h<<<(NXE + 255) / 256, 256>>>(x, xh, xl, NXE);
    conv_weights<<<(4 * NWE) / 256, 256>>>(wq, wk, wv, wo, wqh, wkh, wvh, woh);

    proj_qkv<<<dim3(DM / 128, (BATCH * SEQ) / 128, 3), 256, SMG>>>(
        xh, xl, wqh, wkh, wvh, qbh, qbl, kbh, vth,
        q_scale, k_scale, rope_cos, rope_sin);

    flash_attn<<<dim3(SEQ / 128, NH, BATCH), 256, SMF>>>(qbh, qbl, kbh, vth, ath, atl);

    proj_out<<<dim3(DM / 128, (BATCH * SEQ) / 128), 256, SMG>>>(ath, atl, woh, out);
}

// round 14
// speedup vs baseline: 1.7316x; 1.1224x over previous
#include <cuda_runtime.h>
#include <cuda_fp16.h>
#include <cstdint>
#include <math.h>

#define BATCH 2
#define SEQ 2048
#define DM 1024
#define NH 16
#define HD 64
#define EPSV 1e-6f

// ---------------------------------------------------------------------------
// Scratch (__device__ globals: allocation-free rule)
// ---------------------------------------------------------------------------
__device__ __half g_xh[BATCH * SEQ * DM];
__device__ __half g_xl[BATCH * SEQ * DM];
__device__ __half g_wqh[DM * DM], g_wkh[DM * DM], g_wvh[DM * DM], g_woh[DM * DM];
__device__ __half g_qbh[BATCH * NH * SEQ * HD], g_qbl[BATCH * NH * SEQ * HD];
__device__ __half g_kbh[BATCH * NH * SEQ * HD];
__device__ __half g_vth[BATCH * NH * HD * SEQ];      // [b,h,d,s] fp16
__device__ __half g_ath[BATCH * SEQ * DM], g_atl[BATCH * SEQ * DM];

// ---------------------------------------------------------------------------
// Helpers (non-'a' instructions only: legal under compute_103)
// ---------------------------------------------------------------------------
__device__ __forceinline__ uint32_t smem_to_u32(const void* p) {
    uint32_t a;
    asm("{ .reg .u64 t; cvta.to.shared.u64 t, %1; cvt.u32.u64 %0, t; }" : "=r"(a) : "l"(p));
    return a;
}
#define SMEM_SWIZZLE_128B(o) ((o) ^ (((o) >> 3) & 0x70))

#define CP_ASYNC16(dst, src) \
    asm volatile("cp.async.cg.shared.global [%0], [%1], 16;" :: "r"(dst), "l"(src))
#define CP_COMMIT() asm volatile("cp.async.commit_group;" ::: "memory")
#define CP_WAIT0()  asm volatile("cp.async.wait_group 0;" ::: "memory")
#define CP_WAIT1()  asm volatile("cp.async.wait_group 1;" ::: "memory")

__device__ __forceinline__ void ldm_x4(uint32_t* r, uint32_t addr) {
    asm volatile("ldmatrix.sync.aligned.m8n8.x4.shared.b16 {%0,%1,%2,%3}, [%4];"
                 : "=r"(r[0]), "=r"(r[1]), "=r"(r[2]), "=r"(r[3]) : "r"(addr));
}
__device__ __forceinline__ void mma_f16(float* d, const uint32_t* a, const uint32_t* b) {
    asm volatile("mma.sync.aligned.m16n8k16.row.col.f32.f16.f16.f32 "
        "{%0,%1,%2,%3}, {%4,%5,%6,%7}, {%8,%9}, {%0,%1,%2,%3};"
        : "+f"(d[0]), "+f"(d[1]), "+f"(d[2]), "+f"(d[3])
        : "r"(a[0]), "r"(a[1]), "r"(a[2]), "r"(a[3]), "r"(b[0]), "r"(b[1]));
}
__device__ __forceinline__ uint32_t h2u(__half2 h) { return *reinterpret_cast<uint32_t*>(&h); }

// ---------------------------------------------------------------------------
__global__ void split_f32h(const float* __restrict__ in, __half* __restrict__ h,
                           __half* __restrict__ l, int n)
{
    int i = blockIdx.x * blockDim.x + threadIdx.x;
    if (i < n) {
        float x = in[i];
        __half hi = __float2half_rn(x);
        h[i] = hi;
        l[i] = __float2half_rn(x - __half2float(hi));
    }
}

__global__ void conv_weights(const float* __restrict__ wq, const float* __restrict__ wk,
                             const float* __restrict__ wv, const float* __restrict__ wo,
                             __half* __restrict__ oq, __half* __restrict__ ok,
                             __half* __restrict__ ov, __half* __restrict__ oo)
{
    int i = blockIdx.x * blockDim.x + threadIdx.x;
    int sel = i >> 20, li = i & ((1 << 20) - 1);
    const float* src = sel == 0 ? wq : sel == 1 ? wk : sel == 2 ? wv : wo;
    __half* dst = sel == 0 ? oq : sel == 1 ? ok : sel == 2 ? ov : oo;
    dst[li] = __float2half_rn(src[li]);
}

// ---------------------------------------------------------------------------
// Shared GEMM mainloop: 128x128 tile, BK=64, 2-pass split A(hi+lo) x B(hi).
// ---------------------------------------------------------------------------
#define GEMM_MAINLOOP(Ahp, Alp, Bhp)                                                   \
    auto AH_OFF = [&](int buf) { return base + (uint32_t)buf * 49152u; };              \
    auto AL_OFF = [&](int buf) { return AH_OFF(buf) + 16384u; };                       \
    auto BH_OFF = [&](int buf) { return AH_OFF(buf) + 32768u; };                       \
    float acc[2][8][4];                                                                \
    _Pragma("unroll") for (int i = 0; i < 2; i++)                                      \
        _Pragma("unroll") for (int j = 0; j < 8; j++)                                  \
            _Pragma("unroll") for (int q = 0; q < 4; q++) acc[i][j][q] = 0.f;          \
    auto load_chunk = [&](int c) {                                                     \
        int k0 = c << 6;                                                               \
        int buf = c & 1;                                                               \
        for (int idx = tid; idx < 3072; idx += 256) {                                  \
            int sel = idx >> 10;                                                       \
            int li = idx & 1023;                                                       \
            int row = li >> 3, seg = li & 7;                                           \
            const __half* src;                                                         \
            uint32_t dstb;                                                             \
            if (sel == 0)      { src = Ahp + (size_t)(bm + row) * DM + k0; dstb = AH_OFF(buf); } \
            else if (sel == 1) { src = Alp + (size_t)(bm + row) * DM + k0; dstb = AL_OFF(buf); } \
            else               { src = Bhp + (size_t)(bn + row) * DM + k0; dstb = BH_OFF(buf); } \
            CP_ASYNC16(dstb + SMEM_SWIZZLE_128B((uint32_t)(row * 128 + seg * 16)), src + seg * 8); \
        }                                                                              \
        CP_COMMIT();                                                                   \
    };                                                                                 \
    load_chunk(0);                                                                     \
    const int lr = lane & 15, kh = lane >> 4;                                          \
    const int kc = DM >> 6;                                                            \
    for (int c = 0; c < kc; c++) {                                                     \
        if (c + 1 < kc) { load_chunk(c + 1); CP_WAIT1(); }                             \
        else            { CP_WAIT0(); }                                                \
        __syncthreads();                                                               \
        int buf = c & 1;                                                               \
        _Pragma("unroll") for (int kk = 0; kk < 4; kk++) {                             \
            uint32_t aH[2][4], aL[2][4];                                               \
            _Pragma("unroll") for (int i = 0; i < 2; i++) {                            \
                uint32_t ra = SMEM_SWIZZLE_128B((uint32_t)((wm + i * 16 + lr) * 128 + kk * 32 + kh * 16)); \
                ldm_x4(aH[i], AH_OFF(buf) + ra);                                       \
                ldm_x4(aL[i], AL_OFF(buf) + ra);                                       \
            }                                                                          \
            _Pragma("unroll") for (int j = 0; j < 4; j++) {                            \
                uint32_t bfr[4];                                                       \
                ldm_x4(bfr, BH_OFF(buf) +                                              \
                       SMEM_SWIZZLE_128B((uint32_t)((wn + j * 16 + lr) * 128 + kk * 32 + kh * 16))); \
                uint32_t blo[2] = { bfr[0], bfr[2] };                                  \
                uint32_t bhi[2] = { bfr[1], bfr[3] };                                  \
                _Pragma("unroll") for (int i = 0; i < 2; i++) {                        \
                    mma_f16(acc[i][2 * j],     aH[i], blo);                            \
                    mma_f16(acc[i][2 * j + 1], aH[i], bhi);                            \
                    mma_f16(acc[i][2 * j],     aL[i], blo);                            \
                    mma_f16(acc[i][2 * j + 1], aL[i], bhi);                            \
                }                                                                      \
            }                                                                          \
        }                                                                              \
        __syncthreads();                                                               \
    }

// ---------------------------------------------------------------------------
// Fused Q/K/V projection. blockIdx.z: 0=Q (norm+rope, hi+lo), 1=K (norm+rope, hi),
// 2=V (transposed fp16 [b,h,d,s] via smem staging).
// Q carries 0.125 * log2(e) so flash can use exp2f directly.
// ---------------------------------------------------------------------------
__global__ void __launch_bounds__(256, 2) proj_qkv(
    const __half* __restrict__ Ah, const __half* __restrict__ Al,
    const __half* __restrict__ Wq, const __half* __restrict__ Wk, const __half* __restrict__ Wv,
    __half* __restrict__ QbH, __half* __restrict__ QbL, __half* __restrict__ KbH,
    __half* __restrict__ Vt,
    const float* __restrict__ qscale, const float* __restrict__ kscale,
    const float* __restrict__ cosT, const float* __restrict__ sinT)
{
    extern __shared__ char smem[];
    uint32_t raw = smem_to_u32(smem);
    uint32_t base = (raw + 1023u) & ~1023u;

    const int tid = threadIdx.x;
    const int lane = tid & 31, wid = tid >> 5;
    const int wm = (wid >> 1) * 32;
    const int wn = (wid & 1) * 64;
    const int bm = blockIdx.y * 128;
    const int bn = blockIdx.x * 128;
    const int zb = blockIdx.z;
    const __half* Bh = (zb == 0) ? Wq : (zb == 1) ? Wk : Wv;

    GEMM_MAINLOOP(Ah, Al, Bh)

    const int rl = lane >> 2, cl = (lane & 3) * 2;

    if (zb == 2) {
        __half* st = reinterpret_cast<__half*>(smem + (base - raw));
#pragma unroll
        for (int i = 0; i < 2; i++)
#pragma unroll
            for (int j = 0; j < 8; j++) {
                int row0 = wm + i * 16 + rl;
                int col  = wn + j * 8 + cl;
                st[(col)     * 136 + row0]     = __float2half_rn(acc[i][j][0]);
                st[(col + 1) * 136 + row0]     = __float2half_rn(acc[i][j][1]);
                st[(col)     * 136 + row0 + 8] = __float2half_rn(acc[i][j][2]);
                st[(col + 1) * 136 + row0 + 8] = __float2half_rn(acc[i][j][3]);
            }
        __syncthreads();
        int b = bm >> 11, s0 = bm & (SEQ - 1);
        int hbase = bn >> 6;
        for (int t = tid; t < 2048; t += 256) {
            int col = t >> 4, sc = t & 15;
            uint4 v = *reinterpret_cast<uint4*>(&st[col * 136 + sc * 8]);
            int head = hbase + (col >> 6), d = col & 63;
            *reinterpret_cast<uint4*>(
                Vt + ((size_t)(b * NH + head) * HD + d) * SEQ + s0 + sc * 8) = v;
        }
    } else {
        const int head = (bn >> 6) + (wn >> 6);
        // Q: fold softmax scale AND log2(e): 0.125 * 1.4426950408889634
        const float postmul = (zb == 0) ? 0.18033688011112042f : 1.0f;
        const float* sc = (zb == 0) ? qscale : kscale;
        const bool wantLo = (zb == 0);
#pragma unroll
        for (int i = 0; i < 2; i++) {
#pragma unroll
            for (int half = 0; half < 2; half++) {
                int row = bm + wm + i * 16 + rl + half * 8;
                int b = row >> 11, s = row & (SEQ - 1);
                float ss = 0.f;
#pragma unroll
                for (int j = 0; j < 8; j++) {
                    float a0 = acc[i][j][2 * half], a1 = acc[i][j][2 * half + 1];
                    ss += a0 * a0 + a1 * a1;
                }
                ss += __shfl_xor_sync(0xffffffffu, ss, 1);
                ss += __shfl_xor_sync(0xffffffffu, ss, 2);
                float r = rsqrtf(ss * (1.0f / 64.0f) + EPSV);
                int z = b * NH + head;
                size_t rowoff = ((size_t)z * SEQ + s) * HD;
#pragma unroll
                for (int j = 0; j < 8; j++) {
                    int ch = j * 8 + cl;
                    int f = ch >> 1;
                    float c_ = cosT[s * 32 + f];
                    float sn = sinT[s * 32 + f];
                    float tr = acc[i][j][2 * half] * r * sc[ch];
                    float ti = acc[i][j][2 * half + 1] * r * sc[ch + 1];
                    float ox = (tr * c_ - ti * sn) * postmul;
                    float oy = (tr * sn + ti * c_) * postmul;
                    __half2 hp = __floats2half2_rn(ox, oy);
                    if (wantLo) {
                        *(__half2*)(QbH + rowoff + ch) = hp;
                        float2 hf = __half22float2(hp);
                        *(__half2*)(QbL + rowoff + ch) =
                            __floats2half2_rn(ox - hf.x, oy - hf.y);
                    } else {
                        *(__half2*)(KbH + rowoff + ch) = hp;
                    }
                }
            }
        }
    }
}

// ---------------------------------------------------------------------------
// Output projection: attn(split fp16) x Wo(hi) -> fp32 out
// ---------------------------------------------------------------------------
__global__ void __launch_bounds__(256, 2) proj_out(
    const __half* __restrict__ Ah, const __half* __restrict__ Al,
    const __half* __restrict__ Bhw, float* __restrict__ Cf)
{
    extern __shared__ char smem[];
    uint32_t raw = smem_to_u32(smem);
    uint32_t base = (raw + 1023u) & ~1023u;

    const int tid = threadIdx.x;
    const int lane = tid & 31, wid = tid >> 5;
    const int wm = (wid >> 1) * 32;
    const int wn = (wid & 1) * 64;
    const int bm = blockIdx.y * 128;
    const int bn = blockIdx.x * 128;

    GEMM_MAINLOOP(Ah, Al, Bhw)

    const int rl = lane >> 2, cl = (lane & 3) * 2;
#pragma unroll
    for (int i = 0; i < 2; i++)
#pragma unroll
        for (int j = 0; j < 8; j++) {
            int row0 = bm + wm + i * 16 + rl;
            int col  = bn + wn + j * 8 + cl;
            float2 lo; lo.x = acc[i][j][0]; lo.y = acc[i][j][1];
            float2 hi; hi.x = acc[i][j][2]; hi.y = acc[i][j][3];
            *(float2*)(Cf + (size_t)row0 * DM + col) = lo;
            *(float2*)(Cf + (size_t)(row0 + 8) * DM + col) = hi;
        }
}

// ---------------------------------------------------------------------------
// Fused flash attention, FIXED-MAX softmax, double-buffered K/V, hoisted
// cp.async addressing. P is hi-only in P.V (error enters linearly, ~2^-12;
// Q keeps its residual because exp amplifies score error).
// Grid: (SEQ/128, NH, BATCH), 256 threads (8 warps x 16 q-rows), 64-key tiles.
// ---------------------------------------------------------------------------
__global__ void __launch_bounds__(256, 2) flash_attn(
    const __half* __restrict__ Qh, const __half* __restrict__ Ql,
    const __half* __restrict__ Kh, const __half* __restrict__ Vth,
    __half* __restrict__ Oh, __half* __restrict__ Ol)
{
    extern __shared__ char smem[];
    uint32_t raw = smem_to_u32(smem);
    uint32_t base = (raw + 1023u) & ~1023u;
    const uint32_t QH_OFF = base, QL_OFF = base + 16384u;
    auto KH_OFF = [&](int buf) { return base + 32768u + (uint32_t)buf * 16384u; };
    auto VH_OFF = [&](int buf) { return KH_OFF(buf) + 8192u; };

    const int tid = threadIdx.x;
    const int lane = tid & 31, wid = tid >> 5;
    const int lr = lane & 15, kh4 = lane >> 4;
    const int wm = wid * 16;

    const int z = blockIdx.z * NH + blockIdx.y;
    const int b = blockIdx.z, h = blockIdx.y;
    const int q0 = blockIdx.x * 128;

    const __half* qh = Qh + ((size_t)z * SEQ + q0) * HD;
    const __half* ql = Ql + ((size_t)z * SEQ + q0) * HD;

    // Q (hi+lo) load: joins tile-0's cp.async group
    for (int idx = tid; idx < 2048; idx += 256) {
        bool isH = idx < 1024;
        int li = idx & 1023;
        int row = li >> 3, seg = li & 7;
        const __half* src = (isH ? qh : ql) + (size_t)row * HD + seg * 8;
        uint32_t dst = (isH ? QH_OFF : QL_OFF) + SMEM_SWIZZLE_128B((uint32_t)(row * 128 + seg * 16));
        CP_ASYNC16(dst, src);
    }

    // ---- hoisted K/V load addressing
    const int i0 = tid, i1 = tid + 256;
    const __half* kS0 = Kh + (size_t)z * SEQ * HD + (i0 >> 3) * HD + (i0 & 7) * 8;
    const __half* kS1 = Kh + (size_t)z * SEQ * HD + (i1 >> 3) * HD + (i1 & 7) * 8;
    const __half* vS0 = Vth + (size_t)z * HD * SEQ + (size_t)(i0 >> 3) * SEQ + (i0 & 7) * 8;
    const __half* vS1 = Vth + (size_t)z * HD * SEQ + (size_t)(i1 >> 3) * SEQ + (i1 & 7) * 8;
    const uint32_t kOffs0 = SMEM_SWIZZLE_128B((uint32_t)((i0 >> 3) * 128 + (i0 & 7) * 16));
    const uint32_t kOffs1 = SMEM_SWIZZLE_128B((uint32_t)((i1 >> 3) * 128 + (i1 & 7) * 16));
    const uint32_t kD0[2] = { KH_OFF(0) + kOffs0, KH_OFF(1) + kOffs0 };
    const uint32_t kD1[2] = { KH_OFF(0) + kOffs1, KH_OFF(1) + kOffs1 };
    const uint32_t vD0[2] = { VH_OFF(0) + kOffs0, VH_OFF(1) + kOffs0 };
    const uint32_t vD1[2] = { VH_OFF(0) + kOffs1, VH_OFF(1) + kOffs1 };

    auto load_tile = [&](int buf) {
        CP_ASYNC16(kD0[buf], kS0);
        CP_ASYNC16(kD1[buf], kS1);
        CP_ASYNC16(vD0[buf], vS0);
        CP_ASYNC16(vD1[buf], vS1);
        CP_COMMIT();
        kS0 += 64 * HD; kS1 += 64 * HD;
        vS0 += 64;      vS1 += 64;
    };

    load_tile(0);

    float l_i[2] = { 0.f, 0.f };
    float oacc[8][4];
#pragma unroll
    for (int j = 0; j < 8; j++)
#pragma unroll
        for (int q = 0; q < 4; q++) oacc[j][q] = 0.f;

    const int NT = SEQ / 64;
    for (int c = 0; c < NT; c++) {
        int buf = c & 1;
        if (c + 1 < NT) { load_tile(buf ^ 1); CP_WAIT1(); }
        else            { CP_WAIT0(); }
        __syncthreads();

        // ---- S = Q K^T (2-pass): per-warp 16 x 64, log2-domain scores
        float sacc[8][4];
#pragma unroll
        for (int j = 0; j < 8; j++)
#pragma unroll
            for (int q = 0; q < 4; q++) sacc[j][q] = 0.f;

#pragma unroll
        for (int kk = 0; kk < 4; kk++) {
            uint32_t ra = SMEM_SWIZZLE_128B((uint32_t)((wm + lr) * 128 + kk * 32 + kh4 * 16));
            uint32_t aH[4], aL[4];
            ldm_x4(aH, QH_OFF + ra);
            ldm_x4(aL, QL_OFF + ra);
#pragma unroll
            for (int nf = 0; nf < 4; nf++) {
                uint32_t bh4[4];
                ldm_x4(bh4, KH_OFF(buf) +
                       SMEM_SWIZZLE_128B((uint32_t)((nf * 16 + lr) * 128 + kk * 32 + kh4 * 16)));
                uint32_t blo[2] = { bh4[0], bh4[2] }, bhi[2] = { bh4[1], bh4[3] };
                mma_f16(sacc[2 * nf],     aH, blo);
                mma_f16(sacc[2 * nf + 1], aH, bhi);
                mma_f16(sacc[2 * nf],     aL, blo);
                mma_f16(sacc[2 * nf + 1], aL, bhi);
            }
        }

        // ---- fixed-max softmax: p = 2^s (no max tracking, no rescale)
#pragma unroll
        for (int j = 0; j < 8; j++) {
            sacc[j][0] = exp2f(sacc[j][0]);
            sacc[j][1] = exp2f(sacc[j][1]);
            sacc[j][2] = exp2f(sacc[j][2]);
            sacc[j][3] = exp2f(sacc[j][3]);
            l_i[0] += sacc[j][0] + sacc[j][1];
            l_i[1] += sacc[j][2] + sacc[j][3];
        }

        // ---- O += P V (P hi-only; linear error path)
#pragma unroll
        for (int kk = 0; kk < 4; kk++) {
            uint32_t ah[4] = {
                h2u(__floats2half2_rn(sacc[2 * kk][0],     sacc[2 * kk][1])),
                h2u(__floats2half2_rn(sacc[2 * kk][2],     sacc[2 * kk][3])),
                h2u(__floats2half2_rn(sacc[2 * kk + 1][0], sacc[2 * kk + 1][1])),
                h2u(__floats2half2_rn(sacc[2 * kk + 1][2], sacc[2 * kk + 1][3]))
            };
#pragma unroll
            for (int nfp = 0; nfp < 4; nfp++) {
                uint32_t bh4[4];
                ldm_x4(bh4, VH_OFF(buf) +
                       SMEM_SWIZZLE_128B((uint32_t)((nfp * 16 + lr) * 128 + kk * 32 + kh4 * 16)));
                uint32_t blo[2] = { bh4[0], bh4[2] }, bhi[2] = { bh4[1], bh4[3] };
                mma_f16(oacc[2 * nfp],     ah, blo);
                mma_f16(oacc[2 * nfp + 1], ah, bhi);
            }
        }
        __syncthreads();
    }

    // ---- one deferred row-sum reduction (4-lane groups), then normalize
#pragma unroll
    for (int mk = 1; mk <= 2; mk <<= 1) {
        l_i[0] += __shfl_xor_sync(0xffffffffu, l_i[0], mk);
        l_i[1] += __shfl_xor_sync(0xffffffffu, l_i[1], mk);
    }
    float inv0 = 1.0f / l_i[0], inv1 = 1.0f / l_i[1];
    int row0 = q0 + wm + (lane >> 2);
    int colb = h * HD + (lane & 3) * 2;
#pragma unroll
    for (int j = 0; j < 8; j++) {
        float x0 = oacc[j][0] * inv0, x1 = oacc[j][1] * inv0;
        float x2 = oacc[j][2] * inv1, x3 = oacc[j][3] * inv1;
        size_t off0 = ((size_t)(b * SEQ + row0)) * DM + colb + j * 8;
        size_t off1 = ((size_t)(b * SEQ + row0 + 8)) * DM + colb + j * 8;
        __half2 hp0 = __floats2half2_rn(x0, x1);
        __half2 hp1 = __floats2half2_rn(x2, x3);
        *(__half2*)(Oh + off0) = hp0;
        *(__half2*)(Oh + off1) = hp1;
        float2 f0 = __half22float2(hp0);
        float2 f1 = __half22float2(hp1);
        *(__half2*)(Ol + off0) = __floats2half2_rn(x0 - f0.x, x1 - f0.y);
        *(__half2*)(Ol + off1) = __floats2half2_rn(x2 - f1.x, x3 - f1.y);
    }
}

// ---------------------------------------------------------------------------
extern "C" void kernel_launch(void* const* d_in, const int* in_sizes, int n_in,
                              void* d_out, int out_size)
{
    const float* x        = (const float*)d_in[0];
    const float* wq       = (const float*)d_in[1];
    const float* wk       = (const float*)d_in[2];
    const float* wv       = (const float*)d_in[3];
    const float* wo       = (const float*)d_in[4];
    const float* q_scale  = (const float*)d_in[5];
    const float* k_scale  = (const float*)d_in[6];
    const float* rope_cos = (const float*)d_in[7];
    const float* rope_sin = (const float*)d_in[8];
    float* out = (float*)d_out;

    __half *xh, *xl, *wqh, *wkh, *wvh, *woh;
    __half *qbh, *qbl, *kbh, *vth, *ath, *atl;
    cudaGetSymbolAddress((void**)&xh, g_xh);     cudaGetSymbolAddress((void**)&xl, g_xl);
    cudaGetSymbolAddress((void**)&wqh, g_wqh);   cudaGetSymbolAddress((void**)&wkh, g_wkh);
    cudaGetSymbolAddress((void**)&wvh, g_wvh);   cudaGetSymbolAddress((void**)&woh, g_woh);
    cudaGetSymbolAddress((void**)&qbh, g_qbh);   cudaGetSymbolAddress((void**)&qbl, g_qbl);
    cudaGetSymbolAddress((void**)&kbh, g_kbh);
    cudaGetSymbolAddress((void**)&vth, g_vth);
    cudaGetSymbolAddress((void**)&ath, g_ath);   cudaGetSymbolAddress((void**)&atl, g_atl);

    const int SMG = 1024 + 2 * 49152;            // 99328
    const int SMF = 1024 + 32768 + 2 * 16384;    // 66560 (double-buffered K/V)
    cudaFuncSetAttribute(proj_qkv, cudaFuncAttributeMaxDynamicSharedMemorySize, SMG);
    cudaFuncSetAttribute(proj_out, cudaFuncAttributeMaxDynamicSharedMemorySize, SMG);
    cudaFuncSetAttribute(flash_attn, cudaFuncAttributeMaxDynamicSharedMemorySize, SMF);

    const int NXE = BATCH * SEQ * DM;
    const int NWE = DM * DM;

    split_f32h<<<(NXE + 255) / 256, 256>>>(x, xh, xl, NXE);
    conv_weights<<<(4 * NWE) / 256, 256>>>(wq, wk, wv, wo, wqh, wkh, wvh, woh);

    proj_qkv<<<dim3(DM / 128, (BATCH * SEQ) / 128, 3), 256, SMG>>>(
        xh, xl, wqh, wkh, wvh, qbh, qbl, kbh, vth,
        q_scale, k_scale, rope_cos, rope_sin);

    flash_attn<<<dim3(SEQ / 128, NH, BATCH), 256, SMF>>>(qbh, qbl, kbh, vth, ath, atl);

    proj_out<<<dim3(DM / 128, (BATCH * SEQ) / 128), 256, SMG>>>(ath, atl, woh, out);
}

// round 15
// speedup vs baseline: 1.8757x; 1.0832x over previous
#include <cuda_runtime.h>
#include <cuda_fp16.h>
#include <cstdint>
#include <math.h>

#define BATCH 2
#define SEQ 2048
#define DM 1024
#define NH 16
#define HD 64
#define EPSV 1e-6f

// ---------------------------------------------------------------------------
// Scratch (__device__ globals: allocation-free rule)
// ---------------------------------------------------------------------------
__device__ __half g_xh[BATCH * SEQ * DM];
__device__ __half g_xl[BATCH * SEQ * DM];
__device__ __half g_wqh[DM * DM], g_wkh[DM * DM], g_wvh[DM * DM], g_woh[DM * DM];
__device__ __half g_qbh[BATCH * NH * SEQ * HD], g_qbl[BATCH * NH * SEQ * HD];
__device__ __half g_kbh[BATCH * NH * SEQ * HD];
__device__ __half g_vth[BATCH * NH * HD * SEQ];      // [b,h,d,s] fp16
__device__ __half g_ath[BATCH * SEQ * DM];

// ---------------------------------------------------------------------------
// Helpers (non-'a' instructions only: legal under compute_103)
// ---------------------------------------------------------------------------
__device__ __forceinline__ uint32_t smem_to_u32(const void* p) {
    uint32_t a;
    asm("{ .reg .u64 t; cvta.to.shared.u64 t, %1; cvt.u32.u64 %0, t; }" : "=r"(a) : "l"(p));
    return a;
}
#define SMEM_SWIZZLE_128B(o) ((o) ^ (((o) >> 3) & 0x70))

#define CP_ASYNC16(dst, src) \
    asm volatile("cp.async.cg.shared.global [%0], [%1], 16;" :: "r"(dst), "l"(src))
#define CP_COMMIT() asm volatile("cp.async.commit_group;" ::: "memory")
#define CP_WAIT0()  asm volatile("cp.async.wait_group 0;" ::: "memory")
#define CP_WAIT1()  asm volatile("cp.async.wait_group 1;" ::: "memory")

__device__ __forceinline__ void ldm_x4(uint32_t* r, uint32_t addr) {
    asm volatile("ldmatrix.sync.aligned.m8n8.x4.shared.b16 {%0,%1,%2,%3}, [%4];"
                 : "=r"(r[0]), "=r"(r[1]), "=r"(r[2]), "=r"(r[3]) : "r"(addr));
}
__device__ __forceinline__ void mma_f16(float* d, const uint32_t* a, const uint32_t* b) {
    asm volatile("mma.sync.aligned.m16n8k16.row.col.f32.f16.f16.f32 "
        "{%0,%1,%2,%3}, {%4,%5,%6,%7}, {%8,%9}, {%0,%1,%2,%3};"
        : "+f"(d[0]), "+f"(d[1]), "+f"(d[2]), "+f"(d[3])
        : "r"(a[0]), "r"(a[1]), "r"(a[2]), "r"(a[3]), "r"(b[0]), "r"(b[1]));
}
__device__ __forceinline__ uint32_t h2u(__half2 h) { return *reinterpret_cast<uint32_t*>(&h); }

// ---------------------------------------------------------------------------
__global__ void split_f32h(const float* __restrict__ in, __half* __restrict__ h,
                           __half* __restrict__ l, int n)
{
    int i = blockIdx.x * blockDim.x + threadIdx.x;
    if (i < n) {
        float x = in[i];
        __half hi = __float2half_rn(x);
        h[i] = hi;
        l[i] = __float2half_rn(x - __half2float(hi));
    }
}

__global__ void conv_weights(const float* __restrict__ wq, const float* __restrict__ wk,
                             const float* __restrict__ wv, const float* __restrict__ wo,
                             __half* __restrict__ oq, __half* __restrict__ ok,
                             __half* __restrict__ ov, __half* __restrict__ oo)
{
    int i = blockIdx.x * blockDim.x + threadIdx.x;
    int sel = i >> 20, li = i & ((1 << 20) - 1);
    const float* src = sel == 0 ? wq : sel == 1 ? wk : sel == 2 ? wv : wo;
    __half* dst = sel == 0 ? oq : sel == 1 ? ok : sel == 2 ? ov : oo;
    dst[li] = __float2half_rn(src[li]);
}

// ---------------------------------------------------------------------------
// Fused Q/K/V projection. blockIdx.z: 0=Q (norm+rope, hi+lo), 1=K (norm+rope, hi),
// 2=V (transposed fp16 [b,h,d,s]; x-lo pass SKIPPED — V error path is linear).
// Q carries 0.125 * log2(e) so flash can use exp2f directly.
// ---------------------------------------------------------------------------
__global__ void __launch_bounds__(256, 2) proj_qkv(
    const __half* __restrict__ Ah, const __half* __restrict__ Al,
    const __half* __restrict__ Wq, const __half* __restrict__ Wk, const __half* __restrict__ Wv,
    __half* __restrict__ QbH, __half* __restrict__ QbL, __half* __restrict__ KbH,
    __half* __restrict__ Vt,
    const float* __restrict__ qscale, const float* __restrict__ kscale,
    const float* __restrict__ cosT, const float* __restrict__ sinT)
{
    extern __shared__ char smem[];
    uint32_t raw = smem_to_u32(smem);
    uint32_t base = (raw + 1023u) & ~1023u;

    const int tid = threadIdx.x;
    const int lane = tid & 31, wid = tid >> 5;
    const int wm = (wid >> 1) * 32;
    const int wn = (wid & 1) * 64;
    const int bm = blockIdx.y * 128;
    const int bn = blockIdx.x * 128;
    const int zb = blockIdx.z;
    const bool vmode = (zb == 2);
    const __half* Bh = (zb == 0) ? Wq : (zb == 1) ? Wk : Wv;

    auto AH_OFF = [&](int buf) { return base + (uint32_t)buf * 49152u; };
    auto AL_OFF = [&](int buf) { return AH_OFF(buf) + 16384u; };
    auto BH_OFF = [&](int buf) { return AH_OFF(buf) + 32768u; };

    float acc[2][8][4];
#pragma unroll
    for (int i = 0; i < 2; i++)
#pragma unroll
        for (int j = 0; j < 8; j++)
#pragma unroll
            for (int q = 0; q < 4; q++) acc[i][j][q] = 0.f;

    auto load_chunk = [&](int c) {
        int k0 = c << 6;
        int buf = c & 1;
        for (int idx = tid; idx < 3072; idx += 256) {
            int sel = idx >> 10;            // uniform per iteration (tid<256, step 256)
            if (sel == 1 && vmode) continue; // V: skip x-lo strip
            int li = idx & 1023;
            int row = li >> 3, seg = li & 7;
            const __half* src;
            uint32_t dstb;
            if (sel == 0)      { src = Ah + (size_t)(bm + row) * DM + k0; dstb = AH_OFF(buf); }
            else if (sel == 1) { src = Al + (size_t)(bm + row) * DM + k0; dstb = AL_OFF(buf); }
            else               { src = Bh + (size_t)(bn + row) * DM + k0; dstb = BH_OFF(buf); }
            CP_ASYNC16(dstb + SMEM_SWIZZLE_128B((uint32_t)(row * 128 + seg * 16)), src + seg * 8);
        }
        CP_COMMIT();
    };

    load_chunk(0);
    const int lr = lane & 15, kh = lane >> 4;
    const int kc = DM >> 6;

    for (int c = 0; c < kc; c++) {
        if (c + 1 < kc) { load_chunk(c + 1); CP_WAIT1(); }
        else            { CP_WAIT0(); }
        __syncthreads();
        int buf = c & 1;
#pragma unroll
        for (int kk = 0; kk < 4; kk++) {
            uint32_t aH[2][4], aL[2][4];
#pragma unroll
            for (int i = 0; i < 2; i++) {
                uint32_t ra = SMEM_SWIZZLE_128B((uint32_t)((wm + i * 16 + lr) * 128 + kk * 32 + kh * 16));
                ldm_x4(aH[i], AH_OFF(buf) + ra);
                if (!vmode) ldm_x4(aL[i], AL_OFF(buf) + ra);
            }
#pragma unroll
            for (int j = 0; j < 4; j++) {
                uint32_t bfr[4];
                ldm_x4(bfr, BH_OFF(buf) +
                       SMEM_SWIZZLE_128B((uint32_t)((wn + j * 16 + lr) * 128 + kk * 32 + kh * 16)));
                uint32_t blo[2] = { bfr[0], bfr[2] };
                uint32_t bhi[2] = { bfr[1], bfr[3] };
#pragma unroll
                for (int i = 0; i < 2; i++) {
                    mma_f16(acc[i][2 * j],     aH[i], blo);
                    mma_f16(acc[i][2 * j + 1], aH[i], bhi);
                    if (!vmode) {
                        mma_f16(acc[i][2 * j],     aL[i], blo);
                        mma_f16(acc[i][2 * j + 1], aL[i], bhi);
                    }
                }
            }
        }
        __syncthreads();
    }

    const int rl = lane >> 2, cl = (lane & 3) * 2;

    if (vmode) {
        // ---- V: stage [col][row] fp16 in smem, write [b,h,d,s] with 16B stores
        __half* st = reinterpret_cast<__half*>(smem + (base - raw));
#pragma unroll
        for (int i = 0; i < 2; i++)
#pragma unroll
            for (int j = 0; j < 8; j++) {
                int row0 = wm + i * 16 + rl;
                int col  = wn + j * 8 + cl;
                st[(col)     * 136 + row0]     = __float2half_rn(acc[i][j][0]);
                st[(col + 1) * 136 + row0]     = __float2half_rn(acc[i][j][1]);
                st[(col)     * 136 + row0 + 8] = __float2half_rn(acc[i][j][2]);
                st[(col + 1) * 136 + row0 + 8] = __float2half_rn(acc[i][j][3]);
            }
        __syncthreads();
        int b = bm >> 11, s0 = bm & (SEQ - 1);
        int hbase = bn >> 6;
        for (int t = tid; t < 2048; t += 256) {
            int col = t >> 4, sc = t & 15;
            uint4 v = *reinterpret_cast<uint4*>(&st[col * 136 + sc * 8]);
            int head = hbase + (col >> 6), d = col & 63;
            *reinterpret_cast<uint4*>(
                Vt + ((size_t)(b * NH + head) * HD + d) * SEQ + s0 + sc * 8) = v;
        }
    } else {
        const int head = (bn >> 6) + (wn >> 6);
        // Q: fold softmax scale AND log2(e): 0.125 * 1.4426950408889634
        const float postmul = (zb == 0) ? 0.18033688011112042f : 1.0f;
        const float* sc = (zb == 0) ? qscale : kscale;
        const bool wantLo = (zb == 0);
#pragma unroll
        for (int i = 0; i < 2; i++) {
#pragma unroll
            for (int half = 0; half < 2; half++) {
                int row = bm + wm + i * 16 + rl + half * 8;
                int b = row >> 11, s = row & (SEQ - 1);
                float ss = 0.f;
#pragma unroll
                for (int j = 0; j < 8; j++) {
                    float a0 = acc[i][j][2 * half], a1 = acc[i][j][2 * half + 1];
                    ss += a0 * a0 + a1 * a1;
                }
                ss += __shfl_xor_sync(0xffffffffu, ss, 1);
                ss += __shfl_xor_sync(0xffffffffu, ss, 2);
                float r = rsqrtf(ss * (1.0f / 64.0f) + EPSV);
                int z = b * NH + head;
                size_t rowoff = ((size_t)z * SEQ + s) * HD;
#pragma unroll
                for (int j = 0; j < 8; j++) {
                    int ch = j * 8 + cl;
                    int f = ch >> 1;
                    float c_ = cosT[s * 32 + f];
                    float sn = sinT[s * 32 + f];
                    float tr = acc[i][j][2 * half] * r * sc[ch];
                    float ti = acc[i][j][2 * half + 1] * r * sc[ch + 1];
                    float ox = (tr * c_ - ti * sn) * postmul;
                    float oy = (tr * sn + ti * c_) * postmul;
                    __half2 hp = __floats2half2_rn(ox, oy);
                    if (wantLo) {
                        *(__half2*)(QbH + rowoff + ch) = hp;
                        float2 hf = __half22float2(hp);
                        *(__half2*)(QbL + rowoff + ch) =
                            __floats2half2_rn(ox - hf.x, oy - hf.y);
                    } else {
                        *(__half2*)(KbH + rowoff + ch) = hp;
                    }
                }
            }
        }
    }
}

// ---------------------------------------------------------------------------
// Output projection: attn(hi-only fp16) x Wo(hi) -> fp32 out. SINGLE pass.
// ---------------------------------------------------------------------------
__global__ void __launch_bounds__(256, 2) proj_out(
    const __half* __restrict__ Ahp, const __half* __restrict__ Bhw,
    float* __restrict__ Cf)
{
    extern __shared__ char smem[];
    uint32_t raw = smem_to_u32(smem);
    uint32_t base = (raw + 1023u) & ~1023u;
    auto A_OFF = [&](int buf) { return base + (uint32_t)buf * 32768u; };
    auto B_OFF = [&](int buf) { return A_OFF(buf) + 16384u; };

    const int tid = threadIdx.x;
    const int lane = tid & 31, wid = tid >> 5;
    const int wm = (wid >> 1) * 32;
    const int wn = (wid & 1) * 64;
    const int bm = blockIdx.y * 128;
    const int bn = blockIdx.x * 128;

    float acc[2][8][4];
#pragma unroll
    for (int i = 0; i < 2; i++)
#pragma unroll
        for (int j = 0; j < 8; j++)
#pragma unroll
            for (int q = 0; q < 4; q++) acc[i][j][q] = 0.f;

    auto load_chunk = [&](int c) {
        int k0 = c << 6;
        int buf = c & 1;
        for (int idx = tid; idx < 2048; idx += 256) {
            bool isA = idx < 1024;
            int li = idx & 1023;
            int row = li >> 3, seg = li & 7;
            const __half* src = (isA ? Ahp + (size_t)(bm + row) * DM
                                     : Bhw + (size_t)(bn + row) * DM) + k0 + seg * 8;
            uint32_t dstb = isA ? A_OFF(buf) : B_OFF(buf);
            CP_ASYNC16(dstb + SMEM_SWIZZLE_128B((uint32_t)(row * 128 + seg * 16)), src);
        }
        CP_COMMIT();
    };

    load_chunk(0);
    const int lr = lane & 15, kh = lane >> 4;
    const int kc = DM >> 6;

    for (int c = 0; c < kc; c++) {
        if (c + 1 < kc) { load_chunk(c + 1); CP_WAIT1(); }
        else            { CP_WAIT0(); }
        __syncthreads();
        int buf = c & 1;
#pragma unroll
        for (int kk = 0; kk < 4; kk++) {
            uint32_t aH[2][4];
#pragma unroll
            for (int i = 0; i < 2; i++)
                ldm_x4(aH[i], A_OFF(buf) +
                       SMEM_SWIZZLE_128B((uint32_t)((wm + i * 16 + lr) * 128 + kk * 32 + kh * 16)));
#pragma unroll
            for (int j = 0; j < 4; j++) {
                uint32_t bfr[4];
                ldm_x4(bfr, B_OFF(buf) +
                       SMEM_SWIZZLE_128B((uint32_t)((wn + j * 16 + lr) * 128 + kk * 32 + kh * 16)));
                uint32_t blo[2] = { bfr[0], bfr[2] };
                uint32_t bhi[2] = { bfr[1], bfr[3] };
#pragma unroll
                for (int i = 0; i < 2; i++) {
                    mma_f16(acc[i][2 * j],     aH[i], blo);
                    mma_f16(acc[i][2 * j + 1], aH[i], bhi);
                }
            }
        }
        __syncthreads();
    }

    const int rl = lane >> 2, cl = (lane & 3) * 2;
#pragma unroll
    for (int i = 0; i < 2; i++)
#pragma unroll
        for (int j = 0; j < 8; j++) {
            int row0 = bm + wm + i * 16 + rl;
            int col  = bn + wn + j * 8 + cl;
            float2 lo; lo.x = acc[i][j][0]; lo.y = acc[i][j][1];
            float2 hi; hi.x = acc[i][j][2]; hi.y = acc[i][j][3];
            *(float2*)(Cf + (size_t)row0 * DM + col) = lo;
            *(float2*)(Cf + (size_t)(row0 + 8) * DM + col) = hi;
        }
}

// ---------------------------------------------------------------------------
// Fused flash attention, FIXED-MAX softmax, double-buffered K/V, hoisted
// cp.async addressing. P hi-only in P.V; output hi-only (linear error paths).
// Grid: (SEQ/128, NH, BATCH), 256 threads (8 warps x 16 q-rows), 64-key tiles.
// ---------------------------------------------------------------------------
__global__ void __launch_bounds__(256, 2) flash_attn(
    const __half* __restrict__ Qh, const __half* __restrict__ Ql,
    const __half* __restrict__ Kh, const __half* __restrict__ Vth,
    __half* __restrict__ Oh)
{
    extern __shared__ char smem[];
    uint32_t raw = smem_to_u32(smem);
    uint32_t base = (raw + 1023u) & ~1023u;
    const uint32_t QH_OFF = base, QL_OFF = base + 16384u;
    auto KH_OFF = [&](int buf) { return base + 32768u + (uint32_t)buf * 16384u; };
    auto VH_OFF = [&](int buf) { return KH_OFF(buf) + 8192u; };

    const int tid = threadIdx.x;
    const int lane = tid & 31, wid = tid >> 5;
    const int lr = lane & 15, kh4 = lane >> 4;
    const int wm = wid * 16;

    const int z = blockIdx.z * NH + blockIdx.y;
    const int b = blockIdx.z, h = blockIdx.y;
    const int q0 = blockIdx.x * 128;

    const __half* qh = Qh + ((size_t)z * SEQ + q0) * HD;
    const __half* ql = Ql + ((size_t)z * SEQ + q0) * HD;

    // Q (hi+lo) load: joins tile-0's cp.async group
    for (int idx = tid; idx < 2048; idx += 256) {
        bool isH = idx < 1024;
        int li = idx & 1023;
        int row = li >> 3, seg = li & 7;
        const __half* src = (isH ? qh : ql) + (size_t)row * HD + seg * 8;
        uint32_t dst = (isH ? QH_OFF : QL_OFF) + SMEM_SWIZZLE_128B((uint32_t)(row * 128 + seg * 16));
        CP_ASYNC16(dst, src);
    }

    // ---- hoisted K/V load addressing
    const int i0 = tid, i1 = tid + 256;
    const __half* kS0 = Kh + (size_t)z * SEQ * HD + (i0 >> 3) * HD + (i0 & 7) * 8;
    const __half* kS1 = Kh + (size_t)z * SEQ * HD + (i1 >> 3) * HD + (i1 & 7) * 8;
    const __half* vS0 = Vth + (size_t)z * HD * SEQ + (size_t)(i0 >> 3) * SEQ + (i0 & 7) * 8;
    const __half* vS1 = Vth + (size_t)z * HD * SEQ + (size_t)(i1 >> 3) * SEQ + (i1 & 7) * 8;
    const uint32_t kOffs0 = SMEM_SWIZZLE_128B((uint32_t)((i0 >> 3) * 128 + (i0 & 7) * 16));
    const uint32_t kOffs1 = SMEM_SWIZZLE_128B((uint32_t)((i1 >> 3) * 128 + (i1 & 7) * 16));
    const uint32_t kD0[2] = { KH_OFF(0) + kOffs0, KH_OFF(1) + kOffs0 };
    const uint32_t kD1[2] = { KH_OFF(0) + kOffs1, KH_OFF(1) + kOffs1 };
    const uint32_t vD0[2] = { VH_OFF(0) + kOffs0, VH_OFF(1) + kOffs0 };
    const uint32_t vD1[2] = { VH_OFF(0) + kOffs1, VH_OFF(1) + kOffs1 };

    auto load_tile = [&](int buf) {
        CP_ASYNC16(kD0[buf], kS0);
        CP_ASYNC16(kD1[buf], kS1);
        CP_ASYNC16(vD0[buf], vS0);
        CP_ASYNC16(vD1[buf], vS1);
        CP_COMMIT();
        kS0 += 64 * HD; kS1 += 64 * HD;
        vS0 += 64;      vS1 += 64;
    };

    load_tile(0);

    float l_i[2] = { 0.f, 0.f };
    float oacc[8][4];
#pragma unroll
    for (int j = 0; j < 8; j++)
#pragma unroll
        for (int q = 0; q < 4; q++) oacc[j][q] = 0.f;

    const int NT = SEQ / 64;
    for (int c = 0; c < NT; c++) {
        int buf = c & 1;
        if (c + 1 < NT) { load_tile(buf ^ 1); CP_WAIT1(); }
        else            { CP_WAIT0(); }
        __syncthreads();

        // ---- S = Q K^T (2-pass): per-warp 16 x 64, log2-domain scores
        float sacc[8][4];
#pragma unroll
        for (int j = 0; j < 8; j++)
#pragma unroll
            for (int q = 0; q < 4; q++) sacc[j][q] = 0.f;

#pragma unroll
        for (int kk = 0; kk < 4; kk++) {
            uint32_t ra = SMEM_SWIZZLE_128B((uint32_t)((wm + lr) * 128 + kk * 32 + kh4 * 16));
            uint32_t aH[4], aL[4];
            ldm_x4(aH, QH_OFF + ra);
            ldm_x4(aL, QL_OFF + ra);
#pragma unroll
            for (int nf = 0; nf < 4; nf++) {
                uint32_t bh4[4];
                ldm_x4(bh4, KH_OFF(buf) +
                       SMEM_SWIZZLE_128B((uint32_t)((nf * 16 + lr) * 128 + kk * 32 + kh4 * 16)));
                uint32_t blo[2] = { bh4[0], bh4[2] }, bhi[2] = { bh4[1], bh4[3] };
                mma_f16(sacc[2 * nf],     aH, blo);
                mma_f16(sacc[2 * nf + 1], aH, bhi);
                mma_f16(sacc[2 * nf],     aL, blo);
                mma_f16(sacc[2 * nf + 1], aL, bhi);
            }
        }

        // ---- fixed-max softmax: p = 2^s (no max tracking, no rescale)
#pragma unroll
        for (int j = 0; j < 8; j++) {
            sacc[j][0] = exp2f(sacc[j][0]);
            sacc[j][1] = exp2f(sacc[j][1]);
            sacc[j][2] = exp2f(sacc[j][2]);
            sacc[j][3] = exp2f(sacc[j][3]);
            l_i[0] += sacc[j][0] + sacc[j][1];
            l_i[1] += sacc[j][2] + sacc[j][3];
        }

        // ---- O += P V (P hi-only; linear error path)
#pragma unroll
        for (int kk = 0; kk < 4; kk++) {
            uint32_t ah[4] = {
                h2u(__floats2half2_rn(sacc[2 * kk][0],     sacc[2 * kk][1])),
                h2u(__floats2half2_rn(sacc[2 * kk][2],     sacc[2 * kk][3])),
                h2u(__floats2half2_rn(sacc[2 * kk + 1][0], sacc[2 * kk + 1][1])),
                h2u(__floats2half2_rn(sacc[2 * kk + 1][2], sacc[2 * kk + 1][3]))
            };
#pragma unroll
            for (int nfp = 0; nfp < 4; nfp++) {
                uint32_t bh4[4];
                ldm_x4(bh4, VH_OFF(buf) +
                       SMEM_SWIZZLE_128B((uint32_t)((nfp * 16 + lr) * 128 + kk * 32 + kh4 * 16)));
                uint32_t blo[2] = { bh4[0], bh4[2] }, bhi[2] = { bh4[1], bh4[3] };
                mma_f16(oacc[2 * nfp],     ah, blo);
                mma_f16(oacc[2 * nfp + 1], ah, bhi);
            }
        }
        __syncthreads();
    }

    // ---- one deferred row-sum reduction (4-lane groups), then normalize
#pragma unroll
    for (int mk = 1; mk <= 2; mk <<= 1) {
        l_i[0] += __shfl_xor_sync(0xffffffffu, l_i[0], mk);
        l_i[1] += __shfl_xor_sync(0xffffffffu, l_i[1], mk);
    }
    float inv0 = 1.0f / l_i[0], inv1 = 1.0f / l_i[1];
    int row0 = q0 + wm + (lane >> 2);
    int colb = h * HD + (lane & 3) * 2;
#pragma unroll
    for (int j = 0; j < 8; j++) {
        size_t off0 = ((size_t)(b * SEQ + row0)) * DM + colb + j * 8;
        size_t off1 = ((size_t)(b * SEQ + row0 + 8)) * DM + colb + j * 8;
        *(__half2*)(Oh + off0) = __floats2half2_rn(oacc[j][0] * inv0, oacc[j][1] * inv0);
        *(__half2*)(Oh + off1) = __floats2half2_rn(oacc[j][2] * inv1, oacc[j][3] * inv1);
    }
}

// ---------------------------------------------------------------------------
extern "C" void kernel_launch(void* const* d_in, const int* in_sizes, int n_in,
                              void* d_out, int out_size)
{
    const float* x        = (const float*)d_in[0];
    const float* wq       = (const float*)d_in[1];
    const float* wk       = (const float*)d_in[2];
    const float* wv       = (const float*)d_in[3];
    const float* wo       = (const float*)d_in[4];
    const float* q_scale  = (const float*)d_in[5];
    const float* k_scale  = (const float*)d_in[6];
    const float* rope_cos = (const float*)d_in[7];
    const float* rope_sin = (const float*)d_in[8];
    float* out = (float*)d_out;

    __half *xh, *xl, *wqh, *wkh, *wvh, *woh;
    __half *qbh, *qbl, *kbh, *vth, *ath;
    cudaGetSymbolAddress((void**)&xh, g_xh);     cudaGetSymbolAddress((void**)&xl, g_xl);
    cudaGetSymbolAddress((void**)&wqh, g_wqh);   cudaGetSymbolAddress((void**)&wkh, g_wkh);
    cudaGetSymbolAddress((void**)&wvh, g_wvh);   cudaGetSymbolAddress((void**)&woh, g_woh);
    cudaGetSymbolAddress((void**)&qbh, g_qbh);   cudaGetSymbolAddress((void**)&qbl, g_qbl);
    cudaGetSymbolAddress((void**)&kbh, g_kbh);
    cudaGetSymbolAddress((void**)&vth, g_vth);
    cudaGetSymbolAddress((void**)&ath, g_ath);

    const int SMG = 1024 + 2 * 49152;            // 99328 (proj_qkv)
    const int SMO = 1024 + 2 * 32768;            // 66560 (proj_out single-pass)
    const int SMF = 1024 + 32768 + 2 * 16384;    // 66560 (flash)
    cudaFuncSetAttribute(proj_qkv, cudaFuncAttributeMaxDynamicSharedMemorySize, SMG);
    cudaFuncSetAttribute(proj_out, cudaFuncAttributeMaxDynamicSharedMemorySize, SMO);
    cudaFuncSetAttribute(flash_attn, cudaFuncAttributeMaxDynamicSharedMemorySize, SMF);

    const int NXE = BATCH * SEQ * DM;
    const int NWE = DM * DM;

    split_f32h<<<(NXE + 255) / 256, 256>>>(x, xh, xl, NXE);
    conv_weights<<<(4 * NWE) / 256, 256>>>(wq, wk, wv, wo, wqh, wkh, wvh, woh);

    proj_qkv<<<dim3(DM / 128, (BATCH * SEQ) / 128, 3), 256, SMG>>>(
        xh, xl, wqh, wkh, wvh, qbh, qbl, kbh, vth,
        q_scale, k_scale, rope_cos, rope_sin);

    flash_attn<<<dim3(SEQ / 128, NH, BATCH), 256, SMF>>>(qbh, qbl, kbh, vth, ath);

    proj_out<<<dim3(DM / 128, (BATCH * SEQ) / 128), 256, SMO>>>(ath, woh, out);
}

// round 17
// speedup vs baseline: 2.0799x; 1.1089x over previous
#include <cuda_runtime.h>
#include <cuda_fp16.h>
#include <cstdint>
#include <math.h>

#define BATCH 2
#define SEQ 2048
#define DM 1024
#define NH 16
#define HD 64
#define EPSV 1e-6f

// ---------------------------------------------------------------------------
// Scratch (__device__ globals: allocation-free rule)
// ---------------------------------------------------------------------------
__device__ __half g_xh[BATCH * SEQ * DM];
__device__ __half g_xl[BATCH * SEQ * DM];
__device__ __half g_wqh[DM * DM], g_wkh[DM * DM], g_wvh[DM * DM], g_woh[DM * DM];
__device__ __half g_qbh[BATCH * NH * SEQ * HD];
__device__ __half g_kbh[BATCH * NH * SEQ * HD];
__device__ __half g_vth[BATCH * NH * HD * SEQ];      // [b,h,d,s] fp16
__device__ __half g_ath[BATCH * SEQ * DM];

// ---------------------------------------------------------------------------
// Helpers (non-'a' instructions only: legal under compute_103)
// ---------------------------------------------------------------------------
__device__ __forceinline__ uint32_t smem_to_u32(const void* p) {
    uint32_t a;
    asm("{ .reg .u64 t; cvta.to.shared.u64 t, %1; cvt.u32.u64 %0, t; }" : "=r"(a) : "l"(p));
    return a;
}
#define SMEM_SWIZZLE_128B(o) ((o) ^ (((o) >> 3) & 0x70))

#define CP_ASYNC16(dst, src) \
    asm volatile("cp.async.cg.shared.global [%0], [%1], 16;" :: "r"(dst), "l"(src))
#define CP_COMMIT() asm volatile("cp.async.commit_group;" ::: "memory")
#define CP_WAIT0()  asm volatile("cp.async.wait_group 0;" ::: "memory")
#define CP_WAIT1()  asm volatile("cp.async.wait_group 1;" ::: "memory")

__device__ __forceinline__ void ldm_x4(uint32_t* r, uint32_t addr) {
    asm volatile("ldmatrix.sync.aligned.m8n8.x4.shared.b16 {%0,%1,%2,%3}, [%4];"
                 : "=r"(r[0]), "=r"(r[1]), "=r"(r[2]), "=r"(r[3]) : "r"(addr));
}
__device__ __forceinline__ void mma_f16(float* d, const uint32_t* a, const uint32_t* b) {
    asm volatile("mma.sync.aligned.m16n8k16.row.col.f32.f16.f16.f32 "
        "{%0,%1,%2,%3}, {%4,%5,%6,%7}, {%8,%9}, {%0,%1,%2,%3};"
        : "+f"(d[0]), "+f"(d[1]), "+f"(d[2]), "+f"(d[3])
        : "r"(a[0]), "r"(a[1]), "r"(a[2]), "r"(a[3]), "r"(b[0]), "r"(b[1]));
}
__device__ __forceinline__ uint32_t h2u(__half2 h) { return *reinterpret_cast<uint32_t*>(&h); }

// ---------------------------------------------------------------------------
__global__ void split_f32h(const float* __restrict__ in, __half* __restrict__ h,
                           __half* __restrict__ l, int n)
{
    int i = blockIdx.x * blockDim.x + threadIdx.x;
    if (i < n) {
        float x = in[i];
        __half hi = __float2half_rn(x);
        h[i] = hi;
        l[i] = __float2half_rn(x - __half2float(hi));
    }
}

__global__ void conv_weights(const float* __restrict__ wq, const float* __restrict__ wk,
                             const float* __restrict__ wv, const float* __restrict__ wo,
                             __half* __restrict__ oq, __half* __restrict__ ok,
                             __half* __restrict__ ov, __half* __restrict__ oo)
{
    int i = blockIdx.x * blockDim.x + threadIdx.x;
    int sel = i >> 20, li = i & ((1 << 20) - 1);
    const float* src = sel == 0 ? wq : sel == 1 ? wk : sel == 2 ? wv : wo;
    __half* dst = sel == 0 ? oq : sel == 1 ? ok : sel == 2 ? ov : oo;
    dst[li] = __float2half_rn(src[li]);
}

// ---------------------------------------------------------------------------
// Fused Q/K/V projection. blockIdx.z: 0=Q (norm+rope, hi), 1=K (norm+rope, hi),
// 2=V (transposed fp16 [b,h,d,s]; x-lo pass SKIPPED — V error path is linear).
// Q carries 0.125 * log2(e) so flash can use exp2f directly.
// ---------------------------------------------------------------------------
__global__ void __launch_bounds__(256, 2) proj_qkv(
    const __half* __restrict__ Ah, const __half* __restrict__ Al,
    const __half* __restrict__ Wq, const __half* __restrict__ Wk, const __half* __restrict__ Wv,
    __half* __restrict__ QbH, __half* __restrict__ KbH, __half* __restrict__ Vt,
    const float* __restrict__ qscale, const float* __restrict__ kscale,
    const float* __restrict__ cosT, const float* __restrict__ sinT)
{
    extern __shared__ char smem[];
    uint32_t raw = smem_to_u32(smem);
    uint32_t base = (raw + 1023u) & ~1023u;

    const int tid = threadIdx.x;
    const int lane = tid & 31, wid = tid >> 5;
    const int wm = (wid >> 1) * 32;
    const int wn = (wid & 1) * 64;
    const int bm = blockIdx.y * 128;
    const int bn = blockIdx.x * 128;
    const int zb = blockIdx.z;
    const bool vmode = (zb == 2);
    const __half* Bh = (zb == 0) ? Wq : (zb == 1) ? Wk : Wv;

    auto AH_OFF = [&](int buf) { return base + (uint32_t)buf * 49152u; };
    auto AL_OFF = [&](int buf) { return AH_OFF(buf) + 16384u; };
    auto BH_OFF = [&](int buf) { return AH_OFF(buf) + 32768u; };

    float acc[2][8][4];
#pragma unroll
    for (int i = 0; i < 2; i++)
#pragma unroll
        for (int j = 0; j < 8; j++)
#pragma unroll
            for (int q = 0; q < 4; q++) acc[i][j][q] = 0.f;

    auto load_chunk = [&](int c) {
        int k0 = c << 6;
        int buf = c & 1;
        for (int idx = tid; idx < 3072; idx += 256) {
            int sel = idx >> 10;
            if (sel == 1 && vmode) continue;
            int li = idx & 1023;
            int row = li >> 3, seg = li & 7;
            const __half* src;
            uint32_t dstb;
            if (sel == 0)      { src = Ah + (size_t)(bm + row) * DM + k0; dstb = AH_OFF(buf); }
            else if (sel == 1) { src = Al + (size_t)(bm + row) * DM + k0; dstb = AL_OFF(buf); }
            else               { src = Bh + (size_t)(bn + row) * DM + k0; dstb = BH_OFF(buf); }
            CP_ASYNC16(dstb + SMEM_SWIZZLE_128B((uint32_t)(row * 128 + seg * 16)), src + seg * 8);
        }
        CP_COMMIT();
    };

    load_chunk(0);
    const int lr = lane & 15, kh = lane >> 4;
    const int kc = DM >> 6;

    for (int c = 0; c < kc; c++) {
        if (c + 1 < kc) { load_chunk(c + 1); CP_WAIT1(); }
        else            { CP_WAIT0(); }
        __syncthreads();
        int buf = c & 1;
#pragma unroll
        for (int kk = 0; kk < 4; kk++) {
            uint32_t aH[2][4], aL[2][4];
#pragma unroll
            for (int i = 0; i < 2; i++) {
                uint32_t ra = SMEM_SWIZZLE_128B((uint32_t)((wm + i * 16 + lr) * 128 + kk * 32 + kh * 16));
                ldm_x4(aH[i], AH_OFF(buf) + ra);
                if (!vmode) ldm_x4(aL[i], AL_OFF(buf) + ra);
            }
#pragma unroll
            for (int j = 0; j < 4; j++) {
                uint32_t bfr[4];
                ldm_x4(bfr, BH_OFF(buf) +
                       SMEM_SWIZZLE_128B((uint32_t)((wn + j * 16 + lr) * 128 + kk * 32 + kh * 16)));
                uint32_t blo[2] = { bfr[0], bfr[2] };
                uint32_t bhi[2] = { bfr[1], bfr[3] };
#pragma unroll
                for (int i = 0; i < 2; i++) {
                    mma_f16(acc[i][2 * j],     aH[i], blo);
                    mma_f16(acc[i][2 * j + 1], aH[i], bhi);
                    if (!vmode) {
                        mma_f16(acc[i][2 * j],     aL[i], blo);
                        mma_f16(acc[i][2 * j + 1], aL[i], bhi);
                    }
                }
            }
        }
        __syncthreads();
    }

    const int rl = lane >> 2, cl = (lane & 3) * 2;

    if (vmode) {
        // ---- V: stage [col][row] fp16 in smem, write [b,h,d,s] with 16B stores
        __half* st = reinterpret_cast<__half*>(smem + (base - raw));
#pragma unroll
        for (int i = 0; i < 2; i++)
#pragma unroll
            for (int j = 0; j < 8; j++) {
                int row0 = wm + i * 16 + rl;
                int col  = wn + j * 8 + cl;
                st[(col)     * 136 + row0]     = __float2half_rn(acc[i][j][0]);
                st[(col + 1) * 136 + row0]     = __float2half_rn(acc[i][j][1]);
                st[(col)     * 136 + row0 + 8] = __float2half_rn(acc[i][j][2]);
                st[(col + 1) * 136 + row0 + 8] = __float2half_rn(acc[i][j][3]);
            }
        __syncthreads();
        int b = bm >> 11, s0 = bm & (SEQ - 1);
        int hbase = bn >> 6;
        for (int t = tid; t < 2048; t += 256) {
            int col = t >> 4, sc = t & 15;
            uint4 v = *reinterpret_cast<uint4*>(&st[col * 136 + sc * 8]);
            int head = hbase + (col >> 6), d = col & 63;
            *reinterpret_cast<uint4*>(
                Vt + ((size_t)(b * NH + head) * HD + d) * SEQ + s0 + sc * 8) = v;
        }
    } else {
        const int head = (bn >> 6) + (wn >> 6);
        // Q: fold softmax scale AND log2(e): 0.125 * 1.4426950408889634
        const float postmul = (zb == 0) ? 0.18033688011112042f : 1.0f;
        const float* sc = (zb == 0) ? qscale : kscale;
        __half* dst = (zb == 0) ? QbH : KbH;
#pragma unroll
        for (int i = 0; i < 2; i++) {
#pragma unroll
            for (int half = 0; half < 2; half++) {
                int row = bm + wm + i * 16 + rl + half * 8;
                int b = row >> 11, s = row & (SEQ - 1);
                float ss = 0.f;
#pragma unroll
                for (int j = 0; j < 8; j++) {
                    float a0 = acc[i][j][2 * half], a1 = acc[i][j][2 * half + 1];
                    ss += a0 * a0 + a1 * a1;
                }
                ss += __shfl_xor_sync(0xffffffffu, ss, 1);
                ss += __shfl_xor_sync(0xffffffffu, ss, 2);
                float r = rsqrtf(ss * (1.0f / 64.0f) + EPSV);
                int z = b * NH + head;
                size_t rowoff = ((size_t)z * SEQ + s) * HD;
#pragma unroll
                for (int j = 0; j < 8; j++) {
                    int ch = j * 8 + cl;
                    int f = ch >> 1;
                    float c_ = cosT[s * 32 + f];
                    float sn = sinT[s * 32 + f];
                    float tr = acc[i][j][2 * half] * r * sc[ch];
                    float ti = acc[i][j][2 * half + 1] * r * sc[ch + 1];
                    float ox = (tr * c_ - ti * sn) * postmul;
                    float oy = (tr * sn + ti * c_) * postmul;
                    *(__half2*)(dst + rowoff + ch) = __floats2half2_rn(ox, oy);
                }
            }
        }
    }
}

// ---------------------------------------------------------------------------
// Output projection: attn(hi-only fp16) x Wo(hi) -> fp32 out. SINGLE pass.
// ---------------------------------------------------------------------------
__global__ void __launch_bounds__(256, 2) proj_out(
    const __half* __restrict__ Ahp, const __half* __restrict__ Bhw,
    float* __restrict__ Cf)
{
    extern __shared__ char smem[];
    uint32_t raw = smem_to_u32(smem);
    uint32_t base = (raw + 1023u) & ~1023u;
    auto A_OFF = [&](int buf) { return base + (uint32_t)buf * 32768u; };
    auto B_OFF = [&](int buf) { return A_OFF(buf) + 16384u; };

    const int tid = threadIdx.x;
    const int lane = tid & 31, wid = tid >> 5;
    const int wm = (wid >> 1) * 32;
    const int wn = (wid & 1) * 64;
    const int bm = blockIdx.y * 128;
    const int bn = blockIdx.x * 128;

    float acc[2][8][4];
#pragma unroll
    for (int i = 0; i < 2; i++)
#pragma unroll
        for (int j = 0; j < 8; j++)
#pragma unroll
            for (int q = 0; q < 4; q++) acc[i][j][q] = 0.f;

    auto load_chunk = [&](int c) {
        int k0 = c << 6;
        int buf = c & 1;
        for (int idx = tid; idx < 2048; idx += 256) {
            bool isA = idx < 1024;
            int li = idx & 1023;
            int row = li >> 3, seg = li & 7;
            const __half* src = (isA ? Ahp + (size_t)(bm + row) * DM
                                     : Bhw + (size_t)(bn + row) * DM) + k0 + seg * 8;
            uint32_t dstb = isA ? A_OFF(buf) : B_OFF(buf);
            CP_ASYNC16(dstb + SMEM_SWIZZLE_128B((uint32_t)(row * 128 + seg * 16)), src);
        }
        CP_COMMIT();
    };

    load_chunk(0);
    const int lr = lane & 15, kh = lane >> 4;
    const int kc = DM >> 6;

    for (int c = 0; c < kc; c++) {
        if (c + 1 < kc) { load_chunk(c + 1); CP_WAIT1(); }
        else            { CP_WAIT0(); }
        __syncthreads();
        int buf = c & 1;
#pragma unroll
        for (int kk = 0; kk < 4; kk++) {
            uint32_t aH[2][4];
#pragma unroll
            for (int i = 0; i < 2; i++)
                ldm_x4(aH[i], A_OFF(buf) +
                       SMEM_SWIZZLE_128B((uint32_t)((wm + i * 16 + lr) * 128 + kk * 32 + kh * 16)));
#pragma unroll
            for (int j = 0; j < 4; j++) {
                uint32_t bfr[4];
                ldm_x4(bfr, B_OFF(buf) +
                       SMEM_SWIZZLE_128B((uint32_t)((wn + j * 16 + lr) * 128 + kk * 32 + kh * 16)));
                uint32_t blo[2] = { bfr[0], bfr[2] };
                uint32_t bhi[2] = { bfr[1], bfr[3] };
#pragma unroll
                for (int i = 0; i < 2; i++) {
                    mma_f16(acc[i][2 * j],     aH[i], blo);
                    mma_f16(acc[i][2 * j + 1], aH[i], bhi);
                }
            }
        }
        __syncthreads();
    }

    const int rl = lane >> 2, cl = (lane & 3) * 2;
#pragma unroll
    for (int i = 0; i < 2; i++)
#pragma unroll
        for (int j = 0; j < 8; j++) {
            int row0 = bm + wm + i * 16 + rl;
            int col  = bn + wn + j * 8 + cl;
            float2 lo; lo.x = acc[i][j][0]; lo.y = acc[i][j][1];
            float2 hi; hi.x = acc[i][j][2]; hi.y = acc[i][j][3];
            *(float2*)(Cf + (size_t)row0 * DM + col) = lo;
            *(float2*)(Cf + (size_t)(row0 + 8) * DM + col) = hi;
        }
}

// ---------------------------------------------------------------------------
// Fused flash attention, FIXED-MAX softmax, double-buffered K/V, hoisted
// cp.async addressing. Single-pass fp16 everywhere in-kernel (Q, K, P, V, O
// all hi-only; error budget tracked in quadrature across rounds).
// Grid: (SEQ/128, NH, BATCH), 256 threads (8 warps x 16 q-rows), 64-key tiles.
// ---------------------------------------------------------------------------
__global__ void __launch_bounds__(256, 2) flash_attn(
    const __half* __restrict__ Qh, const __half* __restrict__ Kh,
    const __half* __restrict__ Vth, __half* __restrict__ Oh)
{
    extern __shared__ char smem[];
    uint32_t raw = smem_to_u32(smem);
    uint32_t base = (raw + 1023u) & ~1023u;
    const uint32_t QH_OFF = base;
    auto KH_OFF = [&](int buf) { return base + 16384u + (uint32_t)buf * 16384u; };
    auto VH_OFF = [&](int buf) { return KH_OFF(buf) + 8192u; };

    const int tid = threadIdx.x;
    const int lane = tid & 31, wid = tid >> 5;
    const int lr = lane & 15, kh4 = lane >> 4;
    const int wm = wid * 16;

    const int z = blockIdx.z * NH + blockIdx.y;
    const int b = blockIdx.z, h = blockIdx.y;
    const int q0 = blockIdx.x * 128;

    const __half* qh = Qh + ((size_t)z * SEQ + q0) * HD;

    // Q (hi) load: joins tile-0's cp.async group
    for (int idx = tid; idx < 1024; idx += 256) {
        int row = idx >> 3, seg = idx & 7;
        CP_ASYNC16(QH_OFF + SMEM_SWIZZLE_128B((uint32_t)(row * 128 + seg * 16)),
                   qh + (size_t)row * HD + seg * 8);
    }

    // ---- hoisted K/V load addressing
    const int i0 = tid, i1 = tid + 256;
    const __half* kS0 = Kh + (size_t)z * SEQ * HD + (i0 >> 3) * HD + (i0 & 7) * 8;
    const __half* kS1 = Kh + (size_t)z * SEQ * HD + (i1 >> 3) * HD + (i1 & 7) * 8;
    const __half* vS0 = Vth + (size_t)z * HD * SEQ + (size_t)(i0 >> 3) * SEQ + (i0 & 7) * 8;
    const __half* vS1 = Vth + (size_t)z * HD * SEQ + (size_t)(i1 >> 3) * SEQ + (i1 & 7) * 8;
    const uint32_t kOffs0 = SMEM_SWIZZLE_128B((uint32_t)((i0 >> 3) * 128 + (i0 & 7) * 16));
    const uint32_t kOffs1 = SMEM_SWIZZLE_128B((uint32_t)((i1 >> 3) * 128 + (i1 & 7) * 16));
    const uint32_t kD0[2] = { KH_OFF(0) + kOffs0, KH_OFF(1) + kOffs0 };
    const uint32_t kD1[2] = { KH_OFF(0) + kOffs1, KH_OFF(1) + kOffs1 };
    const uint32_t vD0[2] = { VH_OFF(0) + kOffs0, VH_OFF(1) + kOffs0 };
    const uint32_t vD1[2] = { VH_OFF(0) + kOffs1, VH_OFF(1) + kOffs1 };

    auto load_tile = [&](int buf) {
        CP_ASYNC16(kD0[buf], kS0);
        CP_ASYNC16(kD1[buf], kS1);
        CP_ASYNC16(vD0[buf], vS0);
        CP_ASYNC16(vD1[buf], vS1);
        CP_COMMIT();
        kS0 += 64 * HD; kS1 += 64 * HD;
        vS0 += 64;      vS1 += 64;
    };

    load_tile(0);

    float l_i[2] = { 0.f, 0.f };
    float oacc[8][4];
#pragma unroll
    for (int j = 0; j < 8; j++)
#pragma unroll
        for (int q = 0; q < 4; q++) oacc[j][q] = 0.f;

    const int NT = SEQ / 64;
    for (int c = 0; c < NT; c++) {
        int buf = c & 1;
        if (c + 1 < NT) { load_tile(buf ^ 1); CP_WAIT1(); }
        else            { CP_WAIT0(); }
        __syncthreads();

        // ---- S = Q K^T (single pass): per-warp 16 x 64, log2-domain scores
        float sacc[8][4];
#pragma unroll
        for (int j = 0; j < 8; j++)
#pragma unroll
            for (int q = 0; q < 4; q++) sacc[j][q] = 0.f;

#pragma unroll
        for (int kk = 0; kk < 4; kk++) {
            uint32_t aH[4];
            ldm_x4(aH, QH_OFF + SMEM_SWIZZLE_128B((uint32_t)((wm + lr) * 128 + kk * 32 + kh4 * 16)));
#pragma unroll
            for (int nf = 0; nf < 4; nf++) {
                uint32_t bh4[4];
                ldm_x4(bh4, KH_OFF(buf) +
                       SMEM_SWIZZLE_128B((uint32_t)((nf * 16 + lr) * 128 + kk * 32 + kh4 * 16)));
                uint32_t blo[2] = { bh4[0], bh4[2] }, bhi[2] = { bh4[1], bh4[3] };
                mma_f16(sacc[2 * nf],     aH, blo);
                mma_f16(sacc[2 * nf + 1], aH, bhi);
            }
        }

        // ---- fixed-max softmax: p = 2^s (no max tracking, no rescale)
#pragma unroll
        for (int j = 0; j < 8; j++) {
            sacc[j][0] = exp2f(sacc[j][0]);
            sacc[j][1] = exp2f(sacc[j][1]);
            sacc[j][2] = exp2f(sacc[j][2]);
            sacc[j][3] = exp2f(sacc[j][3]);
            l_i[0] += sacc[j][0] + sacc[j][1];
            l_i[1] += sacc[j][2] + sacc[j][3];
        }

        // ---- O += P V (P hi-only; linear error path)
#pragma unroll
        for (int kk = 0; kk < 4; kk++) {
            uint32_t ah[4] = {
                h2u(__floats2half2_rn(sacc[2 * kk][0],     sacc[2 * kk][1])),
                h2u(__floats2half2_rn(sacc[2 * kk][2],     sacc[2 * kk][3])),
                h2u(__floats2half2_rn(sacc[2 * kk + 1][0], sacc[2 * kk + 1][1])),
                h2u(__floats2half2_rn(sacc[2 * kk + 1][2], sacc[2 * kk + 1][3]))
            };
#pragma unroll
            for (int nfp = 0; nfp < 4; nfp++) {
                uint32_t bh4[4];
                ldm_x4(bh4, VH_OFF(buf) +
                       SMEM_SWIZZLE_128B((uint32_t)((nfp * 16 + lr) * 128 + kk * 32 + kh4 * 16)));
                uint32_t blo[2] = { bh4[0], bh4[2] }, bhi[2] = { bh4[1], bh4[3] };
                mma_f16(oacc[2 * nfp],     ah, blo);
                mma_f16(oacc[2 * nfp + 1], ah, bhi);
            }
        }
        __syncthreads();
    }

    // ---- one deferred row-sum reduction (4-lane groups), then normalize
#pragma unroll
    for (int mk = 1; mk <= 2; mk <<= 1) {
        l_i[0] += __shfl_xor_sync(0xffffffffu, l_i[0], mk);
        l_i[1] += __shfl_xor_sync(0xffffffffu, l_i[1], mk);
    }
    float inv0 = 1.0f / l_i[0], inv1 = 1.0f / l_i[1];
    int row0 = q0 + wm + (lane >> 2);
    int colb = h * HD + (lane & 3) * 2;
#pragma unroll
    for (int j = 0; j < 8; j++) {
        size_t off0 = ((size_t)(b * SEQ + row0)) * DM + colb + j * 8;
        size_t off1 = ((size_t)(b * SEQ + row0 + 8)) * DM + colb + j * 8;
        *(__half2*)(Oh + off0) = __floats2half2_rn(oacc[j][0] * inv0, oacc[j][1] * inv0);
        *(__half2*)(Oh + off1) = __floats2half2_rn(oacc[j][2] * inv1, oacc[j][3] * inv1);
    }
}

// ---------------------------------------------------------------------------
extern "C" void kernel_launch(void* const* d_in, const int* in_sizes, int n_in,
                              void* d_out, int out_size)
{
    const float* x        = (const float*)d_in[0];
    const float* wq       = (const float*)d_in[1];
    const float* wk       = (const float*)d_in[2];
    const float* wv       = (const float*)d_in[3];
    const float* wo       = (const float*)d_in[4];
    const float* q_scale  = (const float*)d_in[5];
    const float* k_scale  = (const float*)d_in[6];
    const float* rope_cos = (const float*)d_in[7];
    const float* rope_sin = (const float*)d_in[8];
    float* out = (float*)d_out;

    __half *xh, *xl, *wqh, *wkh, *wvh, *woh;
    __half *qbh, *kbh, *vth, *ath;
    cudaGetSymbolAddress((void**)&xh, g_xh);     cudaGetSymbolAddress((void**)&xl, g_xl);
    cudaGetSymbolAddress((void**)&wqh, g_wqh);   cudaGetSymbolAddress((void**)&wkh, g_wkh);
    cudaGetSymbolAddress((void**)&wvh, g_wvh);   cudaGetSymbolAddress((void**)&woh, g_woh);
    cudaGetSymbolAddress((void**)&qbh, g_qbh);   cudaGetSymbolAddress((void**)&kbh, g_kbh);
    cudaGetSymbolAddress((void**)&vth, g_vth);
    cudaGetSymbolAddress((void**)&ath, g_ath);

    const int SMG = 1024 + 2 * 49152;            // 99328 (proj_qkv)
    const int SMO = 1024 + 2 * 32768;            // 66560 (proj_out)
    const int SMF = 1024 + 16384 + 2 * 16384;    // 50176 (flash: Q hi + 2 K/V bufs)
    cudaFuncSetAttribute(proj_qkv, cudaFuncAttributeMaxDynamicSharedMemorySize, SMG);
    cudaFuncSetAttribute(proj_out, cudaFuncAttributeMaxDynamicSharedMemorySize, SMO);
    cudaFuncSetAttribute(flash_attn, cudaFuncAttributeMaxDynamicSharedMemorySize, SMF);

    const int NXE = BATCH * SEQ * DM;
    const int NWE = DM * DM;

    split_f32h<<<(NXE + 255) / 256, 256>>>(x, xh, xl, NXE);
    conv_weights<<<(4 * NWE) / 256, 256>>>(wq, wk, wv, wo, wqh, wkh, wvh, woh);

    proj_qkv<<<dim3(DM / 128, (BATCH * SEQ) / 128, 3), 256, SMG>>>(
        xh, xl, wqh, wkh, wvh, qbh, kbh, vth,
        q_scale, k_scale, rope_cos, rope_sin);

    flash_attn<<<dim3(SEQ / 128, NH, BATCH), 256, SMF>>>(qbh, kbh, vth, ath);

    proj_out<<<dim3(DM / 128, (BATCH * SEQ) / 128), 256, SMO>>>(ath, woh, out);
}